// round 1
// baseline (speedup 1.0000x reference)
#include <cuda_runtime.h>

// Problem constants
#define B_    2
#define L_    1024
#define P_    1024
#define T_    2048
#define HID_  2048
#define NH_   32
#define NKV_  8
#define D_    64
#define NREP_ 4
#define SCALE_ 0.125f

// ---------------------------------------------------------------------------
// Scratch (static device arrays; allocation is forbidden)
// ---------------------------------------------------------------------------
__device__ float g_qlin[B_ * L_ * NH_ * D_];    // (B*L, NH*D) from GEMM
__device__ float g_klin[B_ * L_ * NKV_ * D_];   // (B*L, NKV*D)
__device__ float g_vlin[B_ * L_ * NKV_ * D_];
__device__ float g_q  [B_ * NH_ * L_ * D_];     // (B,NH,L,D) rope'd
__device__ float g_k  [B_ * NKV_ * T_ * D_];    // (B,NKV,T,D) full cache
__device__ float g_v  [B_ * NKV_ * T_ * D_];
__device__ float g_att[B_ * L_ * NH_ * D_];     // (B,L,NH*D) attention out

// ---------------------------------------------------------------------------
// FP32 tiled GEMM: C[M,N] = A[M,K] @ W[K,N] (+ bias). All dims % 128/16 == 0.
// Block 256 threads, tile 128x128x16, 8x8 per thread.
// ---------------------------------------------------------------------------
__global__ __launch_bounds__(256) void gemm_kernel(
    const float* __restrict__ A, const float* __restrict__ W,
    const float* __restrict__ bias, float* __restrict__ C,
    int M, int N, int K)
{
    __shared__ float As[16][128];
    __shared__ float Bs[16][128];

    const int bn = blockIdx.x * 128;
    const int bm = blockIdx.y * 128;
    const int tid = threadIdx.x;
    const int tr = tid >> 4;       // 0..15
    const int tc = tid & 15;       // 0..15

    float acc[8][8];
#pragma unroll
    for (int i = 0; i < 8; i++)
#pragma unroll
        for (int j = 0; j < 8; j++) acc[i][j] = 0.f;

    for (int k0 = 0; k0 < K; k0 += 16) {
        // A tile: 128 rows x 16 cols = 512 float4
#pragma unroll
        for (int it = 0; it < 2; it++) {
            int lin4 = tid + it * 256;
            int r = lin4 >> 2, c4 = lin4 & 3;
            float4 v = *(const float4*)(A + (size_t)(bm + r) * K + k0 + c4 * 4);
            As[c4 * 4 + 0][r] = v.x;
            As[c4 * 4 + 1][r] = v.y;
            As[c4 * 4 + 2][r] = v.z;
            As[c4 * 4 + 3][r] = v.w;
        }
        // B tile: 16 rows x 128 cols = 512 float4
#pragma unroll
        for (int it = 0; it < 2; it++) {
            int lin4 = tid + it * 256;
            int r = lin4 >> 5, c4 = lin4 & 31;
            *(float4*)(&Bs[r][c4 * 4]) =
                *(const float4*)(W + (size_t)(k0 + r) * N + bn + c4 * 4);
        }
        __syncthreads();

#pragma unroll
        for (int kk = 0; kk < 16; kk++) {
            float a[8], b[8];
            *(float4*)(a)     = *(const float4*)(&As[kk][tr * 8]);
            *(float4*)(a + 4) = *(const float4*)(&As[kk][tr * 8 + 4]);
            *(float4*)(b)     = *(const float4*)(&Bs[kk][tc * 8]);
            *(float4*)(b + 4) = *(const float4*)(&Bs[kk][tc * 8 + 4]);
#pragma unroll
            for (int i = 0; i < 8; i++)
#pragma unroll
                for (int j = 0; j < 8; j++)
                    acc[i][j] += a[i] * b[j];
        }
        __syncthreads();
    }

#pragma unroll
    for (int i = 0; i < 8; i++) {
        int r = bm + tr * 8 + i;
#pragma unroll
        for (int j = 0; j < 8; j++) {
            int c = bn + tc * 8 + j;
            float bi = bias ? bias[c] : 0.f;
            C[(size_t)r * N + c] = acc[i][j] + bi;
        }
    }
}

// ---------------------------------------------------------------------------
// RoPE for Q + layout change (B,L,NH,D) -> (B,NH,L,D)
// ---------------------------------------------------------------------------
__global__ void rope_q_kernel(const float* __restrict__ qlin,
                              const float* __restrict__ cosb,
                              const float* __restrict__ sinb,
                              float* __restrict__ qout)
{
    int idx = blockIdx.x * blockDim.x + threadIdx.x;
    if (idx >= B_ * L_ * NH_ * D_) return;
    int d = idx & 63;
    int h = (idx >> 6) & 31;
    int l = (idx >> 11) & 1023;
    int b = idx >> 21;
    float v  = qlin[idx];
    int  d2  = (d < 32) ? d + 32 : d - 32;
    float vp = qlin[(idx & ~63) | d2];
    float rot = (d < 32) ? -vp : vp;
    float o = v * cosb[l * 64 + d] + rot * sinb[l * 64 + d];
    qout[(((size_t)(b * NH_ + h)) * L_ + l) * D_ + d] = o;
}

// ---------------------------------------------------------------------------
// RoPE for K + copy V into the full KV cache at positions [P, T)
// ---------------------------------------------------------------------------
__global__ void rope_kv_kernel(const float* __restrict__ klin,
                               const float* __restrict__ vlin,
                               const float* __restrict__ cosb,
                               const float* __restrict__ sinb,
                               float* __restrict__ kfull,
                               float* __restrict__ vfull)
{
    int idx = blockIdx.x * blockDim.x + threadIdx.x;
    if (idx >= B_ * L_ * NKV_ * D_) return;
    int d = idx & 63;
    int h = (idx >> 6) & 7;
    int l = (idx >> 9) & 1023;
    int b = idx >> 19;
    size_t dst = (((size_t)(b * NKV_ + h)) * T_ + (P_ + l)) * D_ + d;

    float v  = klin[idx];
    int  d2  = (d < 32) ? d + 32 : d - 32;
    float vp = klin[(idx & ~63) | d2];
    float rot = (d < 32) ? -vp : vp;
    kfull[dst] = v * cosb[l * 64 + d] + rot * sinb[l * 64 + d];
    vfull[dst] = vlin[idx];
}

// ---------------------------------------------------------------------------
// Copy past KV (B,NKV,P,D) into cache positions [0, P)
// ---------------------------------------------------------------------------
__global__ void copy_past_kernel(const float* __restrict__ pk,
                                 const float* __restrict__ pv,
                                 float* __restrict__ kfull,
                                 float* __restrict__ vfull)
{
    int idx = blockIdx.x * blockDim.x + threadIdx.x;
    if (idx >= B_ * NKV_ * P_ * D_) return;
    int d = idx & 63;
    int t = (idx >> 6) & 1023;
    int h = (idx >> 16) & 7;
    int b = idx >> 19;
    size_t dst = (((size_t)(b * NKV_ + h)) * T_ + t) * D_ + d;
    kfull[dst] = pk[idx];
    vfull[dst] = pv[idx];
}

// ---------------------------------------------------------------------------
// Flash attention (fp32 SIMT). Block: 256 threads, 64 queries x 64-key tiles.
// Q stored transposed [d][i], K transposed [d][j] (float4 compute reads),
// P (probabilities) aliases the K buffer, V natural [j][d].
// Grid: (L/64, NH, B).
// ---------------------------------------------------------------------------
#define ATW 68   // padded row width for transposed tiles (68*4 = 272B, 16B-aligned)

__global__ __launch_bounds__(256) void attn_kernel(
    const float* __restrict__ Q,   // (B,NH,L,D)
    const float* __restrict__ K,   // (B,NKV,T,D)
    const float* __restrict__ V,   // (B,NKV,T,D)
    float* __restrict__ O)         // (B,L,NH*D)
{
    extern __shared__ float sm[];
    float* Qt = sm;                 // [64][ATW] : Qt[d*ATW + i] = Q[i][d]
    float* Kt = sm + 64 * ATW;      // [64][ATW] : Kt[d*ATW + j] = K[j][d]; aliased by Ps[i*ATW + j]
    float* Vs = Kt + 64 * ATW;      // [64][64]  : Vs[j*64 + d]

    const int qt = blockIdx.x;
    const int h  = blockIdx.y;
    const int b  = blockIdx.z;
    const int hk = h >> 2;                  // GQA: 4 query heads per KV head
    const int tid = threadIdx.x;
    const int ty = tid >> 4;                // 0..15 -> rows ty*4..
    const int tx = tid & 15;                // 0..15 -> cols tx*4..
    const int q0 = qt * 64;

    const float* Qbase = Q + ((size_t)(b * NH_ + h) * L_ + q0) * D_;
    const float* Kbase = K + (size_t)(b * NKV_ + hk) * T_ * D_;
    const float* Vbase = V + (size_t)(b * NKV_ + hk) * T_ * D_;

    // Load Q tile transposed
#pragma unroll
    for (int it = 0; it < 4; it++) {
        int lin4 = tid + it * 256;          // 1024 float4
        int r = lin4 >> 4, c4 = lin4 & 15;
        float4 v = *(const float4*)(Qbase + r * 64 + c4 * 4);
        Qt[(c4 * 4 + 0) * ATW + r] = v.x;
        Qt[(c4 * 4 + 1) * ATW + r] = v.y;
        Qt[(c4 * 4 + 2) * ATW + r] = v.z;
        Qt[(c4 * 4 + 3) * ATW + r] = v.w;
    }

    float m_run[4], l_run[4], o_acc[4][4];
#pragma unroll
    for (int i = 0; i < 4; i++) {
        m_run[i] = -1e30f; l_run[i] = 0.f;
#pragma unroll
        for (int u = 0; u < 4; u++) o_acc[i][u] = 0.f;
    }

    const int ntiles = qt + 17;             // last key needed: q0+63+P

    for (int kt = 0; kt < ntiles; kt++) {
        __syncthreads();                    // protect Kt/Vs from previous iteration readers
        const float* kp = Kbase + (size_t)kt * 64 * 64;
        const float* vp = Vbase + (size_t)kt * 64 * 64;
#pragma unroll
        for (int it = 0; it < 4; it++) {
            int lin4 = tid + it * 256;
            int r = lin4 >> 4, c4 = lin4 & 15;
            float4 kv = *(const float4*)(kp + r * 64 + c4 * 4);
            Kt[(c4 * 4 + 0) * ATW + r] = kv.x;
            Kt[(c4 * 4 + 1) * ATW + r] = kv.y;
            Kt[(c4 * 4 + 2) * ATW + r] = kv.z;
            Kt[(c4 * 4 + 3) * ATW + r] = kv.w;
            *(float4*)(Vs + r * 64 + c4 * 4) = *(const float4*)(vp + r * 64 + c4 * 4);
        }
        __syncthreads();

        // S = Q @ K^T  (64x64), thread owns 4x4
        float s[4][4];
#pragma unroll
        for (int i = 0; i < 4; i++)
#pragma unroll
            for (int j = 0; j < 4; j++) s[i][j] = 0.f;

#pragma unroll 8
        for (int kk = 0; kk < 64; kk++) {
            float a[4], bb[4];
            *(float4*)a  = *(const float4*)(Qt + kk * ATW + ty * 4);
            *(float4*)bb = *(const float4*)(Kt + kk * ATW + tx * 4);
#pragma unroll
            for (int i = 0; i < 4; i++)
#pragma unroll
                for (int j = 0; j < 4; j++)
                    s[i][j] += a[i] * bb[j];
        }

        // scale + causal mask (only last tile can be partially masked)
        const bool need_mask = (kt == ntiles - 1);
#pragma unroll
        for (int i = 0; i < 4; i++) {
            int qi = q0 + ty * 4 + i;
#pragma unroll
            for (int j = 0; j < 4; j++) {
                float sv = s[i][j] * SCALE_;
                if (need_mask) {
                    int jg = kt * 64 + tx * 4 + j;
                    if (jg > qi + P_) sv = -1e30f;
                }
                s[i][j] = sv;
            }
        }

        // online softmax (row stats across the 16 tx-threads of each row)
#pragma unroll
        for (int i = 0; i < 4; i++) {
            float mt = fmaxf(fmaxf(s[i][0], s[i][1]), fmaxf(s[i][2], s[i][3]));
#pragma unroll
            for (int off = 1; off < 16; off <<= 1)
                mt = fmaxf(mt, __shfl_xor_sync(0xffffffffu, mt, off));
            float mnew = fmaxf(m_run[i], mt);
            float corr = __expf(m_run[i] - mnew);
            float psum = 0.f;
#pragma unroll
            for (int j = 0; j < 4; j++) {
                float p = __expf(s[i][j] - mnew);
                s[i][j] = p;
                psum += p;
            }
#pragma unroll
            for (int off = 1; off < 16; off <<= 1)
                psum += __shfl_xor_sync(0xffffffffu, psum, off);
            l_run[i] = l_run[i] * corr + psum;
            m_run[i] = mnew;
#pragma unroll
            for (int u = 0; u < 4; u++) o_acc[i][u] *= corr;
        }

        // Store P (aliases Kt buffer): Ps[i*ATW + j]
        __syncthreads();
        float* Ps = Kt;
#pragma unroll
        for (int i = 0; i < 4; i++)
#pragma unroll
            for (int j = 0; j < 4; j++)
                Ps[(ty * 4 + i) * ATW + tx * 4 + j] = s[i][j];
        __syncthreads();

        // O += P @ V  (64x64 @ 64x64), thread owns rows ty*4.., dims tx*4..
#pragma unroll 8
        for (int j = 0; j < 64; j++) {
            float a[4], bb[4];
#pragma unroll
            for (int i = 0; i < 4; i++) a[i] = Ps[(ty * 4 + i) * ATW + j];
            *(float4*)bb = *(const float4*)(Vs + j * 64 + tx * 4);
#pragma unroll
            for (int i = 0; i < 4; i++)
#pragma unroll
                for (int u = 0; u < 4; u++)
                    o_acc[i][u] += a[i] * bb[u];
        }
    }

    // Normalize and write: g_att layout (B, L, NH, D)
#pragma unroll
    for (int i = 0; i < 4; i++) {
        int qi = q0 + ty * 4 + i;
        float inv = 1.f / l_run[i];
        size_t base = (((size_t)b * L_ + qi) * NH_ + h) * D_ + tx * 4;
#pragma unroll
        for (int u = 0; u < 4; u++)
            O[base + u] = o_acc[i][u] * inv;
    }
}

// ---------------------------------------------------------------------------
// Launch
// ---------------------------------------------------------------------------
extern "C" void kernel_launch(void* const* d_in, const int* in_sizes, int n_in,
                              void* d_out, int out_size)
{
    const float* x      = (const float*)d_in[0];
    // d_in[1] = attention_mask (pure causal-with-offset; computed analytically)
    const float* cosb   = (const float*)d_in[2];
    const float* sinb   = (const float*)d_in[3];
    const float* past_k = (const float*)d_in[4];
    const float* past_v = (const float*)d_in[5];
    const float* Wq     = (const float*)d_in[6];
    const float* bq     = (const float*)d_in[7];
    const float* Wk     = (const float*)d_in[8];
    const float* bk     = (const float*)d_in[9];
    const float* Wv     = (const float*)d_in[10];
    const float* bv     = (const float*)d_in[11];
    const float* Wo     = (const float*)d_in[12];
    float* out          = (float*)d_out;

    float *qlin, *klin, *vlin, *qb, *kb, *vb, *attb;
    cudaGetSymbolAddress((void**)&qlin, g_qlin);
    cudaGetSymbolAddress((void**)&klin, g_klin);
    cudaGetSymbolAddress((void**)&vlin, g_vlin);
    cudaGetSymbolAddress((void**)&qb,   g_q);
    cudaGetSymbolAddress((void**)&kb,   g_k);
    cudaGetSymbolAddress((void**)&vb,   g_v);
    cudaGetSymbolAddress((void**)&attb, g_att);

    const int M = B_ * L_;  // 2048

    // QKV projections
    gemm_kernel<<<dim3(HID_ / 128, M / 128), 256>>>(x, Wq, bq, qlin, M, NH_ * D_, HID_);
    gemm_kernel<<<dim3((NKV_ * D_) / 128, M / 128), 256>>>(x, Wk, bk, klin, M, NKV_ * D_, HID_);
    gemm_kernel<<<dim3((NKV_ * D_) / 128, M / 128), 256>>>(x, Wv, bv, vlin, M, NKV_ * D_, HID_);

    // RoPE + cache assembly
    rope_q_kernel<<<(B_ * L_ * NH_ * D_) / 256, 256>>>(qlin, cosb, sinb, qb);
    rope_kv_kernel<<<(B_ * L_ * NKV_ * D_) / 256, 256>>>(klin, vlin, cosb, sinb, kb, vb);
    copy_past_kernel<<<(B_ * NKV_ * P_ * D_) / 256, 256>>>(past_k, past_v, kb, vb);

    // Attention
    const int smem = (64 * ATW + 64 * ATW + 64 * 64) * (int)sizeof(float);  // 51200
    cudaFuncSetAttribute(attn_kernel, cudaFuncAttributeMaxDynamicSharedMemorySize, smem);
    attn_kernel<<<dim3(L_ / 64, NH_, B_), 256, smem>>>(qb, kb, vb, attb);

    // Output projection (no bias)
    gemm_kernel<<<dim3(HID_ / 128, M / 128), 256>>>(attb, Wo, nullptr, out, M, HID_, HID_);
}

// round 7
// speedup vs baseline: 1.5062x; 1.5062x over previous
#include <cuda_runtime.h>
#include <cuda_bf16.h>
#include <cstdint>

// ===========================================================================
// Problem constants
// ===========================================================================
#define B_    2
#define L_    1024
#define P_    1024
#define T_    2048
#define HID_  2048
#define NH_   32
#define NKV_  8
#define D_    64
#define SCALE_ 0.125f

// ===========================================================================
// PTX helpers (baseline ISA only — no tcgen05 on this toolchain's PTX target)
// ===========================================================================
__device__ __forceinline__ uint32_t smem_to_u32(const void* smem_ptr) {
    uint32_t addr;
    asm("{ .reg .u64 tmp; cvta.to.shared.u64 tmp, %1; cvt.u32.u64 %0, tmp; }"
        : "=r"(addr) : "l"(smem_ptr));
    return addr;
}

__device__ __forceinline__ void ldsm_x4(uint32_t (&r)[4], uint32_t addr) {
    asm volatile("ldmatrix.sync.aligned.m8n8.x4.shared.b16 {%0,%1,%2,%3}, [%4];"
        : "=r"(r[0]), "=r"(r[1]), "=r"(r[2]), "=r"(r[3]) : "r"(addr));
}

__device__ __forceinline__ void mma_bf16(float (&d)[4], const uint32_t (&a)[4],
                                         uint32_t b0, uint32_t b1) {
    asm volatile(
        "mma.sync.aligned.m16n8k16.row.col.f32.bf16.bf16.f32 "
        "{%0,%1,%2,%3}, {%4,%5,%6,%7}, {%8,%9}, {%0,%1,%2,%3};"
        : "+f"(d[0]), "+f"(d[1]), "+f"(d[2]), "+f"(d[3])
        : "r"(a[0]), "r"(a[1]), "r"(a[2]), "r"(a[3]), "r"(b0), "r"(b1));
}

__device__ __forceinline__ void cp_async16(uint32_t saddr, const void* gaddr) {
    asm volatile("cp.async.cg.shared.global [%0], [%1], 16;"
        :: "r"(saddr), "l"(gaddr));
}
#define CP_COMMIT() asm volatile("cp.async.commit_group;" ::: "memory")
#define CP_WAIT1()  asm volatile("cp.async.wait_group 1;" ::: "memory")
#define CP_WAIT0()  asm volatile("cp.async.wait_group 0;" ::: "memory")

// ===========================================================================
// Scratch (static device arrays; allocation is forbidden)
// ===========================================================================
__device__ float g_qlin[B_ * L_ * NH_ * D_];
__device__ float g_klin[B_ * L_ * NKV_ * D_];
__device__ float g_vlin[B_ * L_ * NKV_ * D_];
__device__ float g_q  [B_ * NH_ * L_ * D_];
__device__ float g_k  [B_ * NKV_ * T_ * D_];
__device__ float g_v  [B_ * NKV_ * T_ * D_];
__device__ float g_att[B_ * L_ * NH_ * D_];

// split-bf16 operands
__device__ __nv_bfloat16 g_xh [B_ * L_ * HID_];
__device__ __nv_bfloat16 g_xl [B_ * L_ * HID_];
__device__ __nv_bfloat16 g_ath[B_ * L_ * NH_ * D_];
__device__ __nv_bfloat16 g_atl[B_ * L_ * NH_ * D_];
__device__ __nv_bfloat16 g_wqt_h[(NH_ * D_) * HID_];
__device__ __nv_bfloat16 g_wqt_l[(NH_ * D_) * HID_];
__device__ __nv_bfloat16 g_wkt_h[(NKV_ * D_) * HID_];
__device__ __nv_bfloat16 g_wkt_l[(NKV_ * D_) * HID_];
__device__ __nv_bfloat16 g_wvt_h[(NKV_ * D_) * HID_];
__device__ __nv_bfloat16 g_wvt_l[(NKV_ * D_) * HID_];
__device__ __nv_bfloat16 g_wot_h[HID_ * (NH_ * D_)];
__device__ __nv_bfloat16 g_wot_l[HID_ * (NH_ * D_)];

__device__ __forceinline__ void split_bf16(float a, __nv_bfloat16& hi, __nv_bfloat16& lo)
{
    hi = __float2bfloat16_rn(a);
    lo = __float2bfloat16_rn(a - __bfloat162float(hi));
}

// ===========================================================================
// Elementwise split conversion: A[n] fp32 -> H,L bf16
// ===========================================================================
__global__ void convert_split_kernel(const float* __restrict__ A,
                                     __nv_bfloat16* __restrict__ H,
                                     __nv_bfloat16* __restrict__ Lo, int n)
{
    int i = (blockIdx.x * blockDim.x + threadIdx.x) * 4;
    if (i >= n) return;
    float4 v = *(const float4*)(A + i);
    __nv_bfloat16 h0, l0, h1, l1, h2, l2, h3, l3;
    split_bf16(v.x, h0, l0);
    split_bf16(v.y, h1, l1);
    split_bf16(v.z, h2, l2);
    split_bf16(v.w, h3, l3);
    *(__nv_bfloat162*)(H + i)     = __nv_bfloat162(h0, h1);
    *(__nv_bfloat162*)(H + i + 2) = __nv_bfloat162(h2, h3);
    *(__nv_bfloat162*)(Lo + i)     = __nv_bfloat162(l0, l1);
    *(__nv_bfloat162*)(Lo + i + 2) = __nv_bfloat162(l2, l3);
}

// ===========================================================================
// Transpose + split: W[K,N] fp32 -> Th,Tl [N,K] bf16 (K-major)
// ===========================================================================
__global__ void transpose_split_kernel(const float* __restrict__ W,
                                       __nv_bfloat16* __restrict__ Th,
                                       __nv_bfloat16* __restrict__ Tl,
                                       int K, int N)
{
    __shared__ float t[32][33];
    int n0 = blockIdx.x * 32, k0 = blockIdx.y * 32;
    int tx = threadIdx.x, ty = threadIdx.y;   // 32 x 8
#pragma unroll
    for (int i = 0; i < 4; i++)
        t[ty + 8 * i][tx] = W[(size_t)(k0 + ty + 8 * i) * N + n0 + tx];
    __syncthreads();
#pragma unroll
    for (int i = 0; i < 4; i++) {
        float a = t[tx][ty + 8 * i];
        __nv_bfloat16 h, l;
        split_bf16(a, h, l);
        size_t o = (size_t)(n0 + ty + 8 * i) * K + k0 + tx;
        Th[o] = h;
        Tl[o] = l;
    }
}

// ===========================================================================
// Split-bf16 mma.sync GEMM: C[M,N] = A[M,K] @ B[N,K]^T (+ bias)
// A as Ah+Al bf16 [M,K]; B as Bh+Bl bf16 [N,K] (both K-major).
// CTA tile 128x128, K-chunk 32, 8 warps (4 M x 2 N), warp tile 32x64.
// Double-buffered cp.async. Smem rows padded to 80B (ldmatrix conflict-free).
// ===========================================================================
#define SROW_B   80          // bytes per smem row (32 bf16 + 8 pad)
#define TILE_B   (128 * SROW_B)     // 10240
#define BUF_B    (4 * TILE_B)       // 40960 (Ah, Al, Bh, Bl)
#define GEMM_SMEM_BYTES (2 * BUF_B) // 81920

__global__ __launch_bounds__(256) void gemm_mma_kernel(
    const __nv_bfloat16* __restrict__ Ah, const __nv_bfloat16* __restrict__ Al,
    const __nv_bfloat16* __restrict__ Bh, const __nv_bfloat16* __restrict__ Bl,
    const float* __restrict__ bias, float* __restrict__ C, int N, int K)
{
    extern __shared__ char smem[];
    const uint32_t sb = smem_to_u32(smem);
    const int tid = threadIdx.x;
    const int lid = tid & 31;
    const int wid = tid >> 5;
    const int wm = wid & 3;          // 0..3 -> M offset wm*32
    const int wn = wid >> 2;         // 0..1 -> N offset wn*64
    const int bn = blockIdx.x * 128;
    const int bm = blockIdx.y * 128;

    // ---- per-thread cp.async assignment: 64 threads per tile, 8 chunks each
    const int ltile = tid >> 6;                  // 0:Ah 1:Al 2:Bh 3:Bl
    const int lsub  = tid & 63;
    const __nv_bfloat16* gbase =
        (ltile == 0) ? Ah : (ltile == 1) ? Al : (ltile == 2) ? Bh : Bl;
    const int rowbase = (ltile < 2) ? bm : bn;
    const uint32_t stile = sb + ltile * TILE_B;

    // ---- ldmatrix per-lane offsets
    const int arow = (lid & 7) + ((lid >> 3) & 1) * 8;   // A: row within 16
    const int akof = (lid >> 4) * 8;                     // A: k offset 0/8
    const int brow = (lid & 7) + (lid >> 4) * 8;         // B: n within 16
    const int bkof = ((lid >> 3) & 1) * 8;               // B: k offset 0/8

    float acc[2][8][4];
#pragma unroll
    for (int mi = 0; mi < 2; mi++)
#pragma unroll
        for (int ni = 0; ni < 8; ni++)
#pragma unroll
            for (int u = 0; u < 4; u++) acc[mi][ni][u] = 0.f;

    const int nch = K >> 5;

    // prologue: load chunk 0 into buffer 0
    {
        const uint32_t db = stile;
#pragma unroll
        for (int i = 0; i < 8; i++) {
            int idx = lsub + i * 64;
            int r = idx >> 2, c = idx & 3;
            cp_async16(db + (uint32_t)(r * SROW_B + c * 16),
                       gbase + (size_t)(rowbase + r) * K + c * 8);
        }
        CP_COMMIT();
    }

    for (int ch = 0; ch < nch; ch++) {
        if (ch + 1 < nch) {
            const uint32_t db = stile + ((ch + 1) & 1) * BUF_B;
            const int k0 = (ch + 1) << 5;
#pragma unroll
            for (int i = 0; i < 8; i++) {
                int idx = lsub + i * 64;
                int r = idx >> 2, c = idx & 3;
                cp_async16(db + (uint32_t)(r * SROW_B + c * 16),
                           gbase + (size_t)(rowbase + r) * K + k0 + c * 8);
            }
            CP_COMMIT();
            CP_WAIT1();
        } else {
            CP_WAIT0();
        }
        __syncthreads();

        const uint32_t ub  = sb + (ch & 1) * BUF_B;
        const uint32_t uAh = ub;
        const uint32_t uAl = ub + TILE_B;
        const uint32_t uBh = ub + 2 * TILE_B;
        const uint32_t uBl = ub + 3 * TILE_B;

#pragma unroll
        for (int ks = 0; ks < 2; ks++) {
            uint32_t ahf[2][4], alf[2][4], bhf[4][4], blf[4][4];
#pragma unroll
            for (int mi = 0; mi < 2; mi++) {
                uint32_t ao = (uint32_t)((wm * 32 + mi * 16 + arow) * SROW_B +
                                         (ks * 16 + akof) * 2);
                ldsm_x4(ahf[mi], uAh + ao);
                ldsm_x4(alf[mi], uAl + ao);
            }
#pragma unroll
            for (int pr = 0; pr < 4; pr++) {
                uint32_t bo = (uint32_t)((wn * 64 + pr * 16 + brow) * SROW_B +
                                         (ks * 16 + bkof) * 2);
                ldsm_x4(bhf[pr], uBh + bo);
                ldsm_x4(blf[pr], uBl + bo);
            }
#pragma unroll
            for (int mi = 0; mi < 2; mi++)
#pragma unroll
                for (int ni = 0; ni < 8; ni++) {
                    int pr = ni >> 1, s = (ni & 1) * 2;
                    mma_bf16(acc[mi][ni], ahf[mi], bhf[pr][s], bhf[pr][s + 1]);
                    mma_bf16(acc[mi][ni], ahf[mi], blf[pr][s], blf[pr][s + 1]);
                    mma_bf16(acc[mi][ni], alf[mi], bhf[pr][s], bhf[pr][s + 1]);
                }
        }
        __syncthreads();
    }

    // ---- epilogue
#pragma unroll
    for (int mi = 0; mi < 2; mi++) {
        int r0 = bm + wm * 32 + mi * 16 + (lid >> 2);
#pragma unroll
        for (int ni = 0; ni < 8; ni++) {
            int col = bn + wn * 64 + ni * 8 + (lid & 3) * 2;
            float b0 = 0.f, b1 = 0.f;
            if (bias) { b0 = bias[col]; b1 = bias[col + 1]; }
            float2 v0 = make_float2(acc[mi][ni][0] + b0, acc[mi][ni][1] + b1);
            float2 v1 = make_float2(acc[mi][ni][2] + b0, acc[mi][ni][3] + b1);
            *(float2*)(C + (size_t)r0 * N + col)       = v0;
            *(float2*)(C + (size_t)(r0 + 8) * N + col) = v1;
        }
    }
}

// ===========================================================================
// RoPE for Q + layout change (B,L,NH,D) -> (B,NH,L,D)
// ===========================================================================
__global__ void rope_q_kernel(const float* __restrict__ qlin,
                              const float* __restrict__ cosb,
                              const float* __restrict__ sinb,
                              float* __restrict__ qout)
{
    int idx = blockIdx.x * blockDim.x + threadIdx.x;
    if (idx >= B_ * L_ * NH_ * D_) return;
    int d = idx & 63;
    int h = (idx >> 6) & 31;
    int l = (idx >> 11) & 1023;
    int b = idx >> 21;
    float v  = qlin[idx];
    int  d2  = (d < 32) ? d + 32 : d - 32;
    float vp = qlin[(idx & ~63) | d2];
    float rot = (d < 32) ? -vp : vp;
    float o = v * cosb[l * 64 + d] + rot * sinb[l * 64 + d];
    qout[(((size_t)(b * NH_ + h)) * L_ + l) * D_ + d] = o;
}

// ===========================================================================
// RoPE for K + copy V into the full KV cache at positions [P, T)
// ===========================================================================
__global__ void rope_kv_kernel(const float* __restrict__ klin,
                               const float* __restrict__ vlin,
                               const float* __restrict__ cosb,
                               const float* __restrict__ sinb,
                               float* __restrict__ kfull,
                               float* __restrict__ vfull)
{
    int idx = blockIdx.x * blockDim.x + threadIdx.x;
    if (idx >= B_ * L_ * NKV_ * D_) return;
    int d = idx & 63;
    int h = (idx >> 6) & 7;
    int l = (idx >> 9) & 1023;
    int b = idx >> 19;
    size_t dst = (((size_t)(b * NKV_ + h)) * T_ + (P_ + l)) * D_ + d;

    float v  = klin[idx];
    int  d2  = (d < 32) ? d + 32 : d - 32;
    float vp = klin[(idx & ~63) | d2];
    float rot = (d < 32) ? -vp : vp;
    kfull[dst] = v * cosb[l * 64 + d] + rot * sinb[l * 64 + d];
    vfull[dst] = vlin[idx];
}

// ===========================================================================
// Copy past KV (B,NKV,P,D) into cache positions [0, P)
// ===========================================================================
__global__ void copy_past_kernel(const float* __restrict__ pk,
                                 const float* __restrict__ pv,
                                 float* __restrict__ kfull,
                                 float* __restrict__ vfull)
{
    int idx = blockIdx.x * blockDim.x + threadIdx.x;
    if (idx >= B_ * NKV_ * P_ * D_) return;
    int d = idx & 63;
    int t = (idx >> 6) & 1023;
    int h = (idx >> 16) & 7;
    int b = idx >> 19;
    size_t dst = (((size_t)(b * NKV_ + h)) * T_ + t) * D_ + d;
    kfull[dst] = pk[idx];
    vfull[dst] = pv[idx];
}

// ===========================================================================
// Flash attention (fp32 SIMT), unchanged from R1.
// ===========================================================================
#define ATW 68

__global__ __launch_bounds__(256) void attn_kernel(
    const float* __restrict__ Q,
    const float* __restrict__ K,
    const float* __restrict__ V,
    float* __restrict__ O)
{
    extern __shared__ float sm[];
    float* Qt = sm;
    float* Kt = sm + 64 * ATW;
    float* Vs = Kt + 64 * ATW;

    const int qt = blockIdx.x;
    const int h  = blockIdx.y;
    const int b  = blockIdx.z;
    const int hk = h >> 2;
    const int tid = threadIdx.x;
    const int ty = tid >> 4;
    const int tx = tid & 15;
    const int q0 = qt * 64;

    const float* Qbase = Q + ((size_t)(b * NH_ + h) * L_ + q0) * D_;
    const float* Kbase = K + (size_t)(b * NKV_ + hk) * T_ * D_;
    const float* Vbase = V + (size_t)(b * NKV_ + hk) * T_ * D_;

#pragma unroll
    for (int it = 0; it < 4; it++) {
        int lin4 = tid + it * 256;
        int r = lin4 >> 4, c4 = lin4 & 15;
        float4 v = *(const float4*)(Qbase + r * 64 + c4 * 4);
        Qt[(c4 * 4 + 0) * ATW + r] = v.x;
        Qt[(c4 * 4 + 1) * ATW + r] = v.y;
        Qt[(c4 * 4 + 2) * ATW + r] = v.z;
        Qt[(c4 * 4 + 3) * ATW + r] = v.w;
    }

    float m_run[4], l_run[4], o_acc[4][4];
#pragma unroll
    for (int i = 0; i < 4; i++) {
        m_run[i] = -1e30f; l_run[i] = 0.f;
#pragma unroll
        for (int u = 0; u < 4; u++) o_acc[i][u] = 0.f;
    }

    const int ntiles = qt + 17;

    for (int kt = 0; kt < ntiles; kt++) {
        __syncthreads();
        const float* kp = Kbase + (size_t)kt * 64 * 64;
        const float* vp = Vbase + (size_t)kt * 64 * 64;
#pragma unroll
        for (int it = 0; it < 4; it++) {
            int lin4 = tid + it * 256;
            int r = lin4 >> 4, c4 = lin4 & 15;
            float4 kv = *(const float4*)(kp + r * 64 + c4 * 4);
            Kt[(c4 * 4 + 0) * ATW + r] = kv.x;
            Kt[(c4 * 4 + 1) * ATW + r] = kv.y;
            Kt[(c4 * 4 + 2) * ATW + r] = kv.z;
            Kt[(c4 * 4 + 3) * ATW + r] = kv.w;
            *(float4*)(Vs + r * 64 + c4 * 4) = *(const float4*)(vp + r * 64 + c4 * 4);
        }
        __syncthreads();

        float s[4][4];
#pragma unroll
        for (int i = 0; i < 4; i++)
#pragma unroll
            for (int j = 0; j < 4; j++) s[i][j] = 0.f;

#pragma unroll 8
        for (int kk = 0; kk < 64; kk++) {
            float a[4], bb[4];
            *(float4*)a  = *(const float4*)(Qt + kk * ATW + ty * 4);
            *(float4*)bb = *(const float4*)(Kt + kk * ATW + tx * 4);
#pragma unroll
            for (int i = 0; i < 4; i++)
#pragma unroll
                for (int j = 0; j < 4; j++)
                    s[i][j] += a[i] * bb[j];
        }

        const bool need_mask = (kt == ntiles - 1);
#pragma unroll
        for (int i = 0; i < 4; i++) {
            int qi = q0 + ty * 4 + i;
#pragma unroll
            for (int j = 0; j < 4; j++) {
                float sv = s[i][j] * SCALE_;
                if (need_mask) {
                    int jg = kt * 64 + tx * 4 + j;
                    if (jg > qi + P_) sv = -1e30f;
                }
                s[i][j] = sv;
            }
        }

#pragma unroll
        for (int i = 0; i < 4; i++) {
            float mt = fmaxf(fmaxf(s[i][0], s[i][1]), fmaxf(s[i][2], s[i][3]));
#pragma unroll
            for (int off = 1; off < 16; off <<= 1)
                mt = fmaxf(mt, __shfl_xor_sync(0xffffffffu, mt, off));
            float mnew = fmaxf(m_run[i], mt);
            float corr = __expf(m_run[i] - mnew);
            float psum = 0.f;
#pragma unroll
            for (int j = 0; j < 4; j++) {
                float p = __expf(s[i][j] - mnew);
                s[i][j] = p;
                psum += p;
            }
#pragma unroll
            for (int off = 1; off < 16; off <<= 1)
                psum += __shfl_xor_sync(0xffffffffu, psum, off);
            l_run[i] = l_run[i] * corr + psum;
            m_run[i] = mnew;
#pragma unroll
            for (int u = 0; u < 4; u++) o_acc[i][u] *= corr;
        }

        __syncthreads();
        float* Ps = Kt;
#pragma unroll
        for (int i = 0; i < 4; i++)
#pragma unroll
            for (int j = 0; j < 4; j++)
                Ps[(ty * 4 + i) * ATW + tx * 4 + j] = s[i][j];
        __syncthreads();

#pragma unroll 8
        for (int j = 0; j < 64; j++) {
            float a[4], bb[4];
#pragma unroll
            for (int i = 0; i < 4; i++) a[i] = Ps[(ty * 4 + i) * ATW + j];
            *(float4*)bb = *(const float4*)(Vs + j * 64 + tx * 4);
#pragma unroll
            for (int i = 0; i < 4; i++)
#pragma unroll
                for (int u = 0; u < 4; u++)
                    o_acc[i][u] += a[i] * bb[u];
        }
    }

#pragma unroll
    for (int i = 0; i < 4; i++) {
        int qi = q0 + ty * 4 + i;
        float inv = 1.f / l_run[i];
        size_t base = (((size_t)b * L_ + qi) * NH_ + h) * D_ + tx * 4;
#pragma unroll
        for (int u = 0; u < 4; u++)
            O[base + u] = o_acc[i][u] * inv;
    }
}

// ===========================================================================
// Launch
// ===========================================================================
extern "C" void kernel_launch(void* const* d_in, const int* in_sizes, int n_in,
                              void* d_out, int out_size)
{
    const float* x      = (const float*)d_in[0];
    const float* cosb   = (const float*)d_in[2];
    const float* sinb   = (const float*)d_in[3];
    const float* past_k = (const float*)d_in[4];
    const float* past_v = (const float*)d_in[5];
    const float* Wq     = (const float*)d_in[6];
    const float* bq     = (const float*)d_in[7];
    const float* Wk     = (const float*)d_in[8];
    const float* bk     = (const float*)d_in[9];
    const float* Wv     = (const float*)d_in[10];
    const float* bv     = (const float*)d_in[11];
    const float* Wo     = (const float*)d_in[12];
    float* out          = (float*)d_out;

    float *qlin, *klin, *vlin, *qb, *kb, *vb, *attb;
    cudaGetSymbolAddress((void**)&qlin, g_qlin);
    cudaGetSymbolAddress((void**)&klin, g_klin);
    cudaGetSymbolAddress((void**)&vlin, g_vlin);
    cudaGetSymbolAddress((void**)&qb,   g_q);
    cudaGetSymbolAddress((void**)&kb,   g_k);
    cudaGetSymbolAddress((void**)&vb,   g_v);
    cudaGetSymbolAddress((void**)&attb, g_att);

    __nv_bfloat16 *xh, *xl, *ath, *atl;
    __nv_bfloat16 *wqh, *wql, *wkh, *wkl, *wvh, *wvl, *woh, *wol;
    cudaGetSymbolAddress((void**)&xh,  g_xh);
    cudaGetSymbolAddress((void**)&xl,  g_xl);
    cudaGetSymbolAddress((void**)&ath, g_ath);
    cudaGetSymbolAddress((void**)&atl, g_atl);
    cudaGetSymbolAddress((void**)&wqh, g_wqt_h);
    cudaGetSymbolAddress((void**)&wql, g_wqt_l);
    cudaGetSymbolAddress((void**)&wkh, g_wkt_h);
    cudaGetSymbolAddress((void**)&wkl, g_wkt_l);
    cudaGetSymbolAddress((void**)&wvh, g_wvt_h);
    cudaGetSymbolAddress((void**)&wvl, g_wvt_l);
    cudaGetSymbolAddress((void**)&woh, g_wot_h);
    cudaGetSymbolAddress((void**)&wol, g_wot_l);

    const int M = B_ * L_;  // 2048

    cudaFuncSetAttribute(gemm_mma_kernel,
                         cudaFuncAttributeMaxDynamicSharedMemorySize, GEMM_SMEM_BYTES);

    // ---- operand prep ----
    convert_split_kernel<<<(M * HID_) / (256 * 4), 256>>>(x, xh, xl, M * HID_);
    transpose_split_kernel<<<dim3((NH_ * D_) / 32, HID_ / 32), dim3(32, 8)>>>(
        Wq, wqh, wql, HID_, NH_ * D_);
    transpose_split_kernel<<<dim3((NKV_ * D_) / 32, HID_ / 32), dim3(32, 8)>>>(
        Wk, wkh, wkl, HID_, NKV_ * D_);
    transpose_split_kernel<<<dim3((NKV_ * D_) / 32, HID_ / 32), dim3(32, 8)>>>(
        Wv, wvh, wvl, HID_, NKV_ * D_);
    transpose_split_kernel<<<dim3(HID_ / 32, (NH_ * D_) / 32), dim3(32, 8)>>>(
        Wo, woh, wol, NH_ * D_, HID_);

    // ---- QKV projections (mma.sync tensor cores) ----
    gemm_mma_kernel<<<dim3((NH_ * D_) / 128, M / 128), 256, GEMM_SMEM_BYTES>>>(
        xh, xl, wqh, wql, bq, qlin, NH_ * D_, HID_);
    gemm_mma_kernel<<<dim3((NKV_ * D_) / 128, M / 128), 256, GEMM_SMEM_BYTES>>>(
        xh, xl, wkh, wkl, bk, klin, NKV_ * D_, HID_);
    gemm_mma_kernel<<<dim3((NKV_ * D_) / 128, M / 128), 256, GEMM_SMEM_BYTES>>>(
        xh, xl, wvh, wvl, bv, vlin, NKV_ * D_, HID_);

    // ---- RoPE + cache assembly ----
    rope_q_kernel<<<(B_ * L_ * NH_ * D_) / 256, 256>>>(qlin, cosb, sinb, qb);
    rope_kv_kernel<<<(B_ * L_ * NKV_ * D_) / 256, 256>>>(klin, vlin, cosb, sinb, kb, vb);
    copy_past_kernel<<<(B_ * NKV_ * P_ * D_) / 256, 256>>>(past_k, past_v, kb, vb);

    // ---- Attention (fp32 SIMT) ----
    const int smem = (64 * ATW + 64 * ATW + 64 * 64) * (int)sizeof(float);
    cudaFuncSetAttribute(attn_kernel, cudaFuncAttributeMaxDynamicSharedMemorySize, smem);
    attn_kernel<<<dim3(L_ / 64, NH_, B_), 256, smem>>>(qb, kb, vb, attb);

    // ---- Output projection (mma.sync tensor cores) ----
    convert_split_kernel<<<(M * HID_) / (256 * 4), 256>>>(attb, ath, atl, M * HID_);
    gemm_mma_kernel<<<dim3(HID_ / 128, M / 128), 256, GEMM_SMEM_BYTES>>>(
        ath, atl, woh, wol, nullptr, out, HID_, HID_);
}

// round 8
// speedup vs baseline: 2.5250x; 1.6765x over previous
#include <cuda_runtime.h>
#include <cuda_bf16.h>
#include <cstdint>

// ===========================================================================
// Problem constants
// ===========================================================================
#define B_    2
#define L_    1024
#define P_    1024
#define T_    2048
#define HID_  2048
#define NH_   32
#define NKV_  8
#define D_    64
#define SCALE_ 0.125f

// ===========================================================================
// PTX helpers (baseline ISA only — tcgen05 unavailable on this PTX target)
// ===========================================================================
__device__ __forceinline__ uint32_t smem_to_u32(const void* smem_ptr) {
    uint32_t addr;
    asm("{ .reg .u64 tmp; cvta.to.shared.u64 tmp, %1; cvt.u32.u64 %0, tmp; }"
        : "=r"(addr) : "l"(smem_ptr));
    return addr;
}

__device__ __forceinline__ void ldsm_x4(uint32_t (&r)[4], uint32_t addr) {
    asm volatile("ldmatrix.sync.aligned.m8n8.x4.shared.b16 {%0,%1,%2,%3}, [%4];"
        : "=r"(r[0]), "=r"(r[1]), "=r"(r[2]), "=r"(r[3]) : "r"(addr));
}

__device__ __forceinline__ void mma_bf16(float (&d)[4], const uint32_t (&a)[4],
                                         uint32_t b0, uint32_t b1) {
    asm volatile(
        "mma.sync.aligned.m16n8k16.row.col.f32.bf16.bf16.f32 "
        "{%0,%1,%2,%3}, {%4,%5,%6,%7}, {%8,%9}, {%0,%1,%2,%3};"
        : "+f"(d[0]), "+f"(d[1]), "+f"(d[2]), "+f"(d[3])
        : "r"(a[0]), "r"(a[1]), "r"(a[2]), "r"(a[3]), "r"(b0), "r"(b1));
}

__device__ __forceinline__ void cp_async16(uint32_t saddr, const void* gaddr) {
    asm volatile("cp.async.cg.shared.global [%0], [%1], 16;"
        :: "r"(saddr), "l"(gaddr));
}
#define CP_COMMIT() asm volatile("cp.async.commit_group;" ::: "memory")
#define CP_WAIT1()  asm volatile("cp.async.wait_group 1;" ::: "memory")
#define CP_WAIT0()  asm volatile("cp.async.wait_group 0;" ::: "memory")

// ===========================================================================
// Scratch (static device arrays; allocation is forbidden)
// ===========================================================================
__device__ float g_qlin[B_ * L_ * NH_ * D_];
__device__ float g_klin[B_ * L_ * NKV_ * D_];
__device__ float g_vlin[B_ * L_ * NKV_ * D_];

// split-bf16 operands
__device__ __nv_bfloat16 g_xh [B_ * L_ * HID_];
__device__ __nv_bfloat16 g_xl [B_ * L_ * HID_];
__device__ __nv_bfloat16 g_ath[B_ * L_ * NH_ * D_];   // attention out hi
__device__ __nv_bfloat16 g_atl[B_ * L_ * NH_ * D_];   // attention out lo
__device__ __nv_bfloat16 g_wqt_h[(NH_ * D_) * HID_];
__device__ __nv_bfloat16 g_wqt_l[(NH_ * D_) * HID_];
__device__ __nv_bfloat16 g_wkt_h[(NKV_ * D_) * HID_];
__device__ __nv_bfloat16 g_wkt_l[(NKV_ * D_) * HID_];
__device__ __nv_bfloat16 g_wvt_h[(NKV_ * D_) * HID_];
__device__ __nv_bfloat16 g_wvt_l[(NKV_ * D_) * HID_];
__device__ __nv_bfloat16 g_wot_h[HID_ * (NH_ * D_)];
__device__ __nv_bfloat16 g_wot_l[HID_ * (NH_ * D_)];

// attention operands (split bf16)
__device__ __nv_bfloat16 g_qh [B_ * NH_ * L_ * D_];   // (B,NH,L,D)
__device__ __nv_bfloat16 g_ql [B_ * NH_ * L_ * D_];
__device__ __nv_bfloat16 g_kh [B_ * NKV_ * T_ * D_];  // (B,NKV,T,D)
__device__ __nv_bfloat16 g_kl [B_ * NKV_ * T_ * D_];
__device__ __nv_bfloat16 g_vth[B_ * NKV_ * D_ * T_];  // (B,NKV,D,T) transposed
__device__ __nv_bfloat16 g_vtl[B_ * NKV_ * D_ * T_];

__device__ __forceinline__ void split_bf16(float a, __nv_bfloat16& hi, __nv_bfloat16& lo)
{
    hi = __float2bfloat16_rn(a);
    lo = __float2bfloat16_rn(a - __bfloat162float(hi));
}

// pack two floats into split bf16x2 (low half = first arg = even k index)
__device__ __forceinline__ void pack2_split(float x, float y, uint32_t& uh, uint32_t& ul)
{
    __nv_bfloat162 hb = __floats2bfloat162_rn(x, y);
    float lx = x - __bfloat162float(hb.x);
    float ly = y - __bfloat162float(hb.y);
    __nv_bfloat162 lb = __floats2bfloat162_rn(lx, ly);
    uh = *(uint32_t*)&hb;
    ul = *(uint32_t*)&lb;
}

// ===========================================================================
// Elementwise split conversion: A[n] fp32 -> H,L bf16
// ===========================================================================
__global__ void convert_split_kernel(const float* __restrict__ A,
                                     __nv_bfloat16* __restrict__ H,
                                     __nv_bfloat16* __restrict__ Lo, int n)
{
    int i = (blockIdx.x * blockDim.x + threadIdx.x) * 4;
    if (i >= n) return;
    float4 v = *(const float4*)(A + i);
    __nv_bfloat16 h0, l0, h1, l1, h2, l2, h3, l3;
    split_bf16(v.x, h0, l0);
    split_bf16(v.y, h1, l1);
    split_bf16(v.z, h2, l2);
    split_bf16(v.w, h3, l3);
    *(__nv_bfloat162*)(H + i)     = __nv_bfloat162(h0, h1);
    *(__nv_bfloat162*)(H + i + 2) = __nv_bfloat162(h2, h3);
    *(__nv_bfloat162*)(Lo + i)     = __nv_bfloat162(l0, l1);
    *(__nv_bfloat162*)(Lo + i + 2) = __nv_bfloat162(l2, l3);
}

// ===========================================================================
// Transpose + split: W[K,N] fp32 -> Th,Tl [N,K] bf16 (K-major)
// ===========================================================================
__global__ void transpose_split_kernel(const float* __restrict__ W,
                                       __nv_bfloat16* __restrict__ Th,
                                       __nv_bfloat16* __restrict__ Tl,
                                       int K, int N)
{
    __shared__ float t[32][33];
    int n0 = blockIdx.x * 32, k0 = blockIdx.y * 32;
    int tx = threadIdx.x, ty = threadIdx.y;   // 32 x 8
#pragma unroll
    for (int i = 0; i < 4; i++)
        t[ty + 8 * i][tx] = W[(size_t)(k0 + ty + 8 * i) * N + n0 + tx];
    __syncthreads();
#pragma unroll
    for (int i = 0; i < 4; i++) {
        float a = t[tx][ty + 8 * i];
        __nv_bfloat16 h, l;
        split_bf16(a, h, l);
        size_t o = (size_t)(n0 + ty + 8 * i) * K + k0 + tx;
        Th[o] = h;
        Tl[o] = l;
    }
}

// ===========================================================================
// Split-bf16 mma.sync GEMM: C[M,N] = A[M,K] @ B[N,K]^T (+ bias) — as in R7
// ===========================================================================
#define SROW_B   80
#define TILE_B   (128 * SROW_B)
#define BUF_B    (4 * TILE_B)
#define GEMM_SMEM_BYTES (2 * BUF_B)

__global__ __launch_bounds__(256) void gemm_mma_kernel(
    const __nv_bfloat16* __restrict__ Ah, const __nv_bfloat16* __restrict__ Al,
    const __nv_bfloat16* __restrict__ Bh, const __nv_bfloat16* __restrict__ Bl,
    const float* __restrict__ bias, float* __restrict__ C, int N, int K)
{
    extern __shared__ char smem[];
    const uint32_t sb = smem_to_u32(smem);
    const int tid = threadIdx.x;
    const int lid = tid & 31;
    const int wid = tid >> 5;
    const int wm = wid & 3;
    const int wn = wid >> 2;
    const int bn = blockIdx.x * 128;
    const int bm = blockIdx.y * 128;

    const int ltile = tid >> 6;
    const int lsub  = tid & 63;
    const __nv_bfloat16* gbase =
        (ltile == 0) ? Ah : (ltile == 1) ? Al : (ltile == 2) ? Bh : Bl;
    const int rowbase = (ltile < 2) ? bm : bn;
    const uint32_t stile = sb + ltile * TILE_B;

    const int arow = (lid & 7) + ((lid >> 3) & 1) * 8;
    const int akof = (lid >> 4) * 8;
    const int brow = (lid & 7) + (lid >> 4) * 8;
    const int bkof = ((lid >> 3) & 1) * 8;

    float acc[2][8][4];
#pragma unroll
    for (int mi = 0; mi < 2; mi++)
#pragma unroll
        for (int ni = 0; ni < 8; ni++)
#pragma unroll
            for (int u = 0; u < 4; u++) acc[mi][ni][u] = 0.f;

    const int nch = K >> 5;

    {
        const uint32_t db = stile;
#pragma unroll
        for (int i = 0; i < 8; i++) {
            int idx = lsub + i * 64;
            int r = idx >> 2, c = idx & 3;
            cp_async16(db + (uint32_t)(r * SROW_B + c * 16),
                       gbase + (size_t)(rowbase + r) * K + c * 8);
        }
        CP_COMMIT();
    }

    for (int ch = 0; ch < nch; ch++) {
        if (ch + 1 < nch) {
            const uint32_t db = stile + ((ch + 1) & 1) * BUF_B;
            const int k0 = (ch + 1) << 5;
#pragma unroll
            for (int i = 0; i < 8; i++) {
                int idx = lsub + i * 64;
                int r = idx >> 2, c = idx & 3;
                cp_async16(db + (uint32_t)(r * SROW_B + c * 16),
                           gbase + (size_t)(rowbase + r) * K + k0 + c * 8);
            }
            CP_COMMIT();
            CP_WAIT1();
        } else {
            CP_WAIT0();
        }
        __syncthreads();

        const uint32_t ub  = sb + (ch & 1) * BUF_B;
        const uint32_t uAh = ub;
        const uint32_t uAl = ub + TILE_B;
        const uint32_t uBh = ub + 2 * TILE_B;
        const uint32_t uBl = ub + 3 * TILE_B;

#pragma unroll
        for (int ks = 0; ks < 2; ks++) {
            uint32_t ahf[2][4], alf[2][4], bhf[4][4], blf[4][4];
#pragma unroll
            for (int mi = 0; mi < 2; mi++) {
                uint32_t ao = (uint32_t)((wm * 32 + mi * 16 + arow) * SROW_B +
                                         (ks * 16 + akof) * 2);
                ldsm_x4(ahf[mi], uAh + ao);
                ldsm_x4(alf[mi], uAl + ao);
            }
#pragma unroll
            for (int pr = 0; pr < 4; pr++) {
                uint32_t bo = (uint32_t)((wn * 64 + pr * 16 + brow) * SROW_B +
                                         (ks * 16 + bkof) * 2);
                ldsm_x4(bhf[pr], uBh + bo);
                ldsm_x4(blf[pr], uBl + bo);
            }
#pragma unroll
            for (int mi = 0; mi < 2; mi++)
#pragma unroll
                for (int ni = 0; ni < 8; ni++) {
                    int pr = ni >> 1, s = (ni & 1) * 2;
                    mma_bf16(acc[mi][ni], ahf[mi], bhf[pr][s], bhf[pr][s + 1]);
                    mma_bf16(acc[mi][ni], ahf[mi], blf[pr][s], blf[pr][s + 1]);
                    mma_bf16(acc[mi][ni], alf[mi], bhf[pr][s], bhf[pr][s + 1]);
                }
        }
        __syncthreads();
    }

#pragma unroll
    for (int mi = 0; mi < 2; mi++) {
        int r0 = bm + wm * 32 + mi * 16 + (lid >> 2);
#pragma unroll
        for (int ni = 0; ni < 8; ni++) {
            int col = bn + wn * 64 + ni * 8 + (lid & 3) * 2;
            float b0 = 0.f, b1 = 0.f;
            if (bias) { b0 = bias[col]; b1 = bias[col + 1]; }
            float2 v0 = make_float2(acc[mi][ni][0] + b0, acc[mi][ni][1] + b1);
            float2 v1 = make_float2(acc[mi][ni][2] + b0, acc[mi][ni][3] + b1);
            *(float2*)(C + (size_t)r0 * N + col)       = v0;
            *(float2*)(C + (size_t)(r0 + 8) * N + col) = v1;
        }
    }
}

// ===========================================================================
// RoPE for Q: qlin (B,L,NH,D) fp32 -> split bf16 (B,NH,L,D)
// ===========================================================================
__global__ void rope_q_kernel(const float* __restrict__ qlin,
                              const float* __restrict__ cosb,
                              const float* __restrict__ sinb,
                              __nv_bfloat16* __restrict__ qh,
                              __nv_bfloat16* __restrict__ ql)
{
    int idx = blockIdx.x * blockDim.x + threadIdx.x;
    if (idx >= B_ * L_ * NH_ * D_) return;
    int d = idx & 63;
    int h = (idx >> 6) & 31;
    int l = (idx >> 11) & 1023;
    int b = idx >> 21;
    float v  = qlin[idx];
    int  d2  = (d < 32) ? d + 32 : d - 32;
    float vp = qlin[(idx & ~63) | d2];
    float rot = (d < 32) ? -vp : vp;
    float o = v * cosb[l * 64 + d] + rot * sinb[l * 64 + d];
    __nv_bfloat16 hi, lo;
    split_bf16(o, hi, lo);
    size_t dst = (((size_t)(b * NH_ + h)) * L_ + l) * D_ + d;
    qh[dst] = hi;
    ql[dst] = lo;
}

// ===========================================================================
// RoPE for K: klin (B,L,NKV,D) fp32 -> split bf16 cache at [P, T)
// ===========================================================================
__global__ void rope_k_kernel(const float* __restrict__ klin,
                              const float* __restrict__ cosb,
                              const float* __restrict__ sinb,
                              __nv_bfloat16* __restrict__ kh,
                              __nv_bfloat16* __restrict__ kl)
{
    int idx = blockIdx.x * blockDim.x + threadIdx.x;
    if (idx >= B_ * L_ * NKV_ * D_) return;
    int d = idx & 63;
    int h = (idx >> 6) & 7;
    int l = (idx >> 9) & 1023;
    int b = idx >> 19;
    float v  = klin[idx];
    int  d2  = (d < 32) ? d + 32 : d - 32;
    float vp = klin[(idx & ~63) | d2];
    float rot = (d < 32) ? -vp : vp;
    float o = v * cosb[l * 64 + d] + rot * sinb[l * 64 + d];
    __nv_bfloat16 hi, lo;
    split_bf16(o, hi, lo);
    size_t dst = (((size_t)(b * NKV_ + h)) * T_ + (P_ + l)) * D_ + d;
    kh[dst] = hi;
    kl[dst] = lo;
}

// ===========================================================================
// Copy + split past K (B,NKV,P,D) into cache positions [0, P)
// ===========================================================================
__global__ void copy_past_k_kernel(const float* __restrict__ pk,
                                   __nv_bfloat16* __restrict__ kh,
                                   __nv_bfloat16* __restrict__ kl)
{
    int idx = blockIdx.x * blockDim.x + threadIdx.x;
    if (idx >= B_ * NKV_ * P_ * D_) return;
    int d = idx & 63;
    int t = (idx >> 6) & 1023;
    int h = (idx >> 16) & 7;
    int b = idx >> 19;
    __nv_bfloat16 hi, lo;
    split_bf16(pk[idx], hi, lo);
    size_t dst = (((size_t)(b * NKV_ + h)) * T_ + t) * D_ + d;
    kh[dst] = hi;
    kl[dst] = lo;
}

// ===========================================================================
// Transpose + split V (new): vlin (B,L,NKV,D) -> (B,NKV,D,T) at [P, T)
// grid (D/32, L/32, B*NKV), block (32, 8)
// ===========================================================================
__global__ void transpose_v_new_kernel(const float* __restrict__ vlin,
                                       __nv_bfloat16* __restrict__ vth,
                                       __nv_bfloat16* __restrict__ vtl)
{
    __shared__ float t[32][33];
    int bh = blockIdx.z;
    int b = bh >> 3, h = bh & 7;
    int l0 = blockIdx.y * 32, d0 = blockIdx.x * 32;
    int tx = threadIdx.x, ty = threadIdx.y;
#pragma unroll
    for (int i = 0; i < 4; i++)
        t[ty + 8 * i][tx] =
            vlin[(((size_t)(b * L_ + l0 + ty + 8 * i)) * NKV_ + h) * D_ + d0 + tx];
    __syncthreads();
#pragma unroll
    for (int i = 0; i < 4; i++) {
        float a = t[tx][ty + 8 * i];
        __nv_bfloat16 hi, lo;
        split_bf16(a, hi, lo);
        size_t dst = (((size_t)(b * NKV_ + h)) * D_ + d0 + ty + 8 * i) * T_ +
                     P_ + l0 + tx;
        vth[dst] = hi;
        vtl[dst] = lo;
    }
}

// ===========================================================================
// Transpose + split V (past): past_v (B,NKV,P,D) -> (B,NKV,D,T) at [0, P)
// grid (D/32, P/32, B*NKV), block (32, 8)
// ===========================================================================
__global__ void transpose_v_past_kernel(const float* __restrict__ pv,
                                        __nv_bfloat16* __restrict__ vth,
                                        __nv_bfloat16* __restrict__ vtl)
{
    __shared__ float t[32][33];
    int bh = blockIdx.z;
    int l0 = blockIdx.y * 32, d0 = blockIdx.x * 32;
    int tx = threadIdx.x, ty = threadIdx.y;
#pragma unroll
    for (int i = 0; i < 4; i++)
        t[ty + 8 * i][tx] =
            pv[((size_t)bh * P_ + l0 + ty + 8 * i) * D_ + d0 + tx];
    __syncthreads();
#pragma unroll
    for (int i = 0; i < 4; i++) {
        float a = t[tx][ty + 8 * i];
        __nv_bfloat16 hi, lo;
        split_bf16(a, hi, lo);
        size_t dst = ((size_t)bh * D_ + d0 + ty + 8 * i) * T_ + l0 + tx;
        vth[dst] = hi;
        vtl[dst] = lo;
    }
}

// ===========================================================================
// Tensor-core flash attention, split-bf16 QK^T and PV.
// CTA: 128 queries (8 warps x 16 rows), KV tile 64, double-buffered cp.async.
// smem rows padded to 72 bf16 (144B) — ldmatrix conflict-free.
// Writes split-bf16 output (B,L,NH,D) directly for the O projection.
// ===========================================================================
#define VROW   72
#define QT_B   (128 * VROW * 2)   // 18432 per Q tile
#define KT_B   (64 * VROW * 2)    // 9216 per K/V tile
#define KVBUF  (4 * KT_B)         // 36864 per stage
#define ATTN_SMEM (2 * QT_B + 2 * KVBUF)   // 110592

__global__ __launch_bounds__(256) void attn_mma_kernel(
    const __nv_bfloat16* __restrict__ Qh, const __nv_bfloat16* __restrict__ Ql,
    const __nv_bfloat16* __restrict__ Kh, const __nv_bfloat16* __restrict__ Kl,
    const __nv_bfloat16* __restrict__ Vth, const __nv_bfloat16* __restrict__ Vtl,
    __nv_bfloat16* __restrict__ Oh, __nv_bfloat16* __restrict__ Ol)
{
    extern __shared__ char smem[];
    const uint32_t sb = smem_to_u32(smem);
    const uint32_t sQh = sb;
    const uint32_t sQl = sb + QT_B;
    const uint32_t sKV = sb + 2 * QT_B;

    const int tid = threadIdx.x;
    const int lid = tid & 31;
    const int wid = tid >> 5;
    const int qb  = (L_ / 128 - 1) - blockIdx.x;   // heavy blocks first
    const int h   = blockIdx.y;
    const int b   = blockIdx.z;
    const int hk  = h >> 2;
    const int q0  = qb * 128;
    const int ntiles = (P_ + q0 + 128) / 64;       // 18 + 2*qb

    const int arow = (lid & 7) + ((lid >> 3) & 1) * 8;
    const int akof = (lid >> 4) * 8;
    const int brow = (lid & 7) + (lid >> 4) * 8;
    const int bkof = ((lid >> 3) & 1) * 8;

    const __nv_bfloat16* qh_base = Qh + ((size_t)(b * NH_ + h) * L_ + q0) * D_;
    const __nv_bfloat16* ql_base = Ql + ((size_t)(b * NH_ + h) * L_ + q0) * D_;
    const __nv_bfloat16* kh_base = Kh + (size_t)(b * NKV_ + hk) * T_ * D_;
    const __nv_bfloat16* kl_base = Kl + (size_t)(b * NKV_ + hk) * T_ * D_;
    const __nv_bfloat16* vh_base = Vth + (size_t)(b * NKV_ + hk) * D_ * T_;
    const __nv_bfloat16* vl_base = Vtl + (size_t)(b * NKV_ + hk) * D_ * T_;

    // ---- cp.async assignment for KV stage: tile = tid>>6 (Kh,Kl,Vh,Vl)
    const int ltile = tid >> 6;
    const int lsub  = tid & 63;
    const __nv_bfloat16* kvg =
        (ltile == 0) ? kh_base : (ltile == 1) ? kl_base :
        (ltile == 2) ? vh_base : vl_base;
    const bool isV = (ltile >= 2);
    const uint32_t kvs_off = (uint32_t)(ltile * KT_B);

    // ---- prologue: issue KV tile 0 into stage 0
    {
        const uint32_t db = sKV + kvs_off;
#pragma unroll
        for (int i = 0; i < 8; i++) {
            int chunk = lsub + i * 64;
            int r = chunk >> 3, c = chunk & 7;
            const __nv_bfloat16* src = isV
                ? kvg + (size_t)r * T_ + c * 8          // Vt rows = dims, cols = keys
                : kvg + (size_t)r * D_ + c * 8;         // K rows = keys
            cp_async16(db + (uint32_t)(r * 144 + c * 16), src);
        }
        CP_COMMIT();
    }

    // ---- load Q tiles (plain): 2 tiles x 1024 chunks
#pragma unroll
    for (int t = 0; t < 2; t++) {
        const __nv_bfloat16* src = t ? ql_base : qh_base;
        const uint32_t dstb = t ? sQl : sQh;
#pragma unroll
        for (int i = 0; i < 4; i++) {
            int chunk = tid + i * 256;
            int r = chunk >> 3, c = chunk & 7;
            uint4 v = *(const uint4*)(src + (size_t)r * D_ + c * 8);
            *(uint4*)(smem + (dstb - sb) + r * 144 + c * 16) = v;
        }
    }

    // ---- state
    float o[8][4];
#pragma unroll
    for (int ni = 0; ni < 8; ni++)
#pragma unroll
        for (int u = 0; u < 4; u++) o[ni][u] = 0.f;
    float m1 = -1e30f, m2 = -1e30f, l1 = 0.f, l2 = 0.f;

    const int qi1 = q0 + wid * 16 + (lid >> 2);
    const int qi2 = qi1 + 8;
    const int lim1 = qi1 + P_;
    const int lim2 = qi2 + P_;

    for (int kt = 0; kt < ntiles; kt++) {
        // issue next tile
        if (kt + 1 < ntiles) {
            const uint32_t db = sKV + ((kt + 1) & 1) * KVBUF + kvs_off;
            const int t0 = (kt + 1) * 64;
#pragma unroll
            for (int i = 0; i < 8; i++) {
                int chunk = lsub + i * 64;
                int r = chunk >> 3, c = chunk & 7;
                const __nv_bfloat16* src = isV
                    ? kvg + (size_t)r * T_ + t0 + c * 8
                    : kvg + (size_t)(t0 + r) * D_ + c * 8;
                cp_async16(db + (uint32_t)(r * 144 + c * 16), src);
            }
            CP_COMMIT();
            CP_WAIT1();
        } else {
            CP_WAIT0();
        }
        __syncthreads();

        const uint32_t ub  = sKV + (kt & 1) * KVBUF;
        const uint32_t uKh = ub;
        const uint32_t uKl = ub + KT_B;
        const uint32_t uVh = ub + 2 * KT_B;
        const uint32_t uVl = ub + 3 * KT_B;

        // ---- S = Q K^T (split, 3 terms)
        float s[8][4];
#pragma unroll
        for (int ni = 0; ni < 8; ni++)
#pragma unroll
            for (int u = 0; u < 4; u++) s[ni][u] = 0.f;

#pragma unroll
        for (int ks = 0; ks < 4; ks++) {
            uint32_t ahf[4], alf[4];
            uint32_t ao = (uint32_t)((wid * 16 + arow) * 144 + (ks * 16 + akof) * 2);
            ldsm_x4(ahf, sQh + ao);
            ldsm_x4(alf, sQl + ao);
#pragma unroll
            for (int pr = 0; pr < 4; pr++) {
                uint32_t bhf[4], blf[4];
                uint32_t bo = (uint32_t)((pr * 16 + brow) * 144 + (ks * 16 + bkof) * 2);
                ldsm_x4(bhf, uKh + bo);
                ldsm_x4(blf, uKl + bo);
#pragma unroll
                for (int t = 0; t < 2; t++) {
                    int ni = 2 * pr + t, s2 = t * 2;
                    mma_bf16(s[ni], ahf, bhf[s2], bhf[s2 + 1]);
                    mma_bf16(s[ni], ahf, blf[s2], blf[s2 + 1]);
                    mma_bf16(s[ni], alf, bhf[s2], bhf[s2 + 1]);
                }
            }
        }

        // ---- scale + mask
#pragma unroll
        for (int ni = 0; ni < 8; ni++)
#pragma unroll
            for (int u = 0; u < 4; u++) s[ni][u] *= SCALE_;

        if (kt >= ntiles - 2) {
            int jc = kt * 64 + 2 * (lid & 3);
#pragma unroll
            for (int ni = 0; ni < 8; ni++) {
                int j = jc + 8 * ni;
                if (j     > lim1) s[ni][0] = -1e30f;
                if (j + 1 > lim1) s[ni][1] = -1e30f;
                if (j     > lim2) s[ni][2] = -1e30f;
                if (j + 1 > lim2) s[ni][3] = -1e30f;
            }
        }

        // ---- online softmax (rows r and r+8)
        float mx1 = -1e30f, mx2 = -1e30f;
#pragma unroll
        for (int ni = 0; ni < 8; ni++) {
            mx1 = fmaxf(mx1, fmaxf(s[ni][0], s[ni][1]));
            mx2 = fmaxf(mx2, fmaxf(s[ni][2], s[ni][3]));
        }
        mx1 = fmaxf(mx1, __shfl_xor_sync(0xffffffffu, mx1, 1));
        mx1 = fmaxf(mx1, __shfl_xor_sync(0xffffffffu, mx1, 2));
        mx2 = fmaxf(mx2, __shfl_xor_sync(0xffffffffu, mx2, 1));
        mx2 = fmaxf(mx2, __shfl_xor_sync(0xffffffffu, mx2, 2));

        float mn1 = fmaxf(m1, mx1), mn2 = fmaxf(m2, mx2);
        float c1 = __expf(m1 - mn1), c2 = __expf(m2 - mn2);
        m1 = mn1; m2 = mn2;

        float p1 = 0.f, p2 = 0.f;
#pragma unroll
        for (int ni = 0; ni < 8; ni++) {
            s[ni][0] = __expf(s[ni][0] - mn1);
            s[ni][1] = __expf(s[ni][1] - mn1);
            s[ni][2] = __expf(s[ni][2] - mn2);
            s[ni][3] = __expf(s[ni][3] - mn2);
            p1 += s[ni][0] + s[ni][1];
            p2 += s[ni][2] + s[ni][3];
        }
        p1 += __shfl_xor_sync(0xffffffffu, p1, 1);
        p1 += __shfl_xor_sync(0xffffffffu, p1, 2);
        p2 += __shfl_xor_sync(0xffffffffu, p2, 1);
        p2 += __shfl_xor_sync(0xffffffffu, p2, 2);
        l1 = l1 * c1 + p1;
        l2 = l2 * c2 + p2;

#pragma unroll
        for (int ni = 0; ni < 8; ni++) {
            o[ni][0] *= c1; o[ni][1] *= c1;
            o[ni][2] *= c2; o[ni][3] *= c2;
        }

        // ---- O += P V  (P from registers, split; V from smem, split)
#pragma unroll
        for (int ks = 0; ks < 4; ks++) {
            uint32_t aPh[4], aPl[4];
            pack2_split(s[2 * ks][0],     s[2 * ks][1],     aPh[0], aPl[0]);
            pack2_split(s[2 * ks][2],     s[2 * ks][3],     aPh[1], aPl[1]);
            pack2_split(s[2 * ks + 1][0], s[2 * ks + 1][1], aPh[2], aPl[2]);
            pack2_split(s[2 * ks + 1][2], s[2 * ks + 1][3], aPh[3], aPl[3]);
#pragma unroll
            for (int pr = 0; pr < 4; pr++) {
                uint32_t bvh[4], bvl[4];
                uint32_t bo = (uint32_t)((pr * 16 + brow) * 144 + (ks * 16 + bkof) * 2);
                ldsm_x4(bvh, uVh + bo);
                ldsm_x4(bvl, uVl + bo);
#pragma unroll
                for (int t = 0; t < 2; t++) {
                    int ni = 2 * pr + t, s2 = t * 2;
                    mma_bf16(o[ni], aPh, bvh[s2], bvh[s2 + 1]);
                    mma_bf16(o[ni], aPh, bvl[s2], bvl[s2 + 1]);
                    mma_bf16(o[ni], aPl, bvh[s2], bvh[s2 + 1]);
                }
            }
        }
        __syncthreads();
    }

    // ---- normalize + split write: (B, L, NH, D)
    float inv1 = 1.f / l1, inv2 = 1.f / l2;
    size_t base1 = (((size_t)b * L_ + qi1) * NH_ + h) * D_;
    size_t base2 = (((size_t)b * L_ + qi2) * NH_ + h) * D_;
#pragma unroll
    for (int ni = 0; ni < 8; ni++) {
        int d = 8 * ni + 2 * (lid & 3);
        uint32_t uh, ul;
        pack2_split(o[ni][0] * inv1, o[ni][1] * inv1, uh, ul);
        *(uint32_t*)(Oh + base1 + d) = uh;
        *(uint32_t*)(Ol + base1 + d) = ul;
        pack2_split(o[ni][2] * inv2, o[ni][3] * inv2, uh, ul);
        *(uint32_t*)(Oh + base2 + d) = uh;
        *(uint32_t*)(Ol + base2 + d) = ul;
    }
}

// ===========================================================================
// Launch
// ===========================================================================
extern "C" void kernel_launch(void* const* d_in, const int* in_sizes, int n_in,
                              void* d_out, int out_size)
{
    const float* x      = (const float*)d_in[0];
    const float* cosb   = (const float*)d_in[2];
    const float* sinb   = (const float*)d_in[3];
    const float* past_k = (const float*)d_in[4];
    const float* past_v = (const float*)d_in[5];
    const float* Wq     = (const float*)d_in[6];
    const float* bq     = (const float*)d_in[7];
    const float* Wk     = (const float*)d_in[8];
    const float* bk     = (const float*)d_in[9];
    const float* Wv     = (const float*)d_in[10];
    const float* bv     = (const float*)d_in[11];
    const float* Wo     = (const float*)d_in[12];
    float* out          = (float*)d_out;

    float *qlin, *klin, *vlin;
    cudaGetSymbolAddress((void**)&qlin, g_qlin);
    cudaGetSymbolAddress((void**)&klin, g_klin);
    cudaGetSymbolAddress((void**)&vlin, g_vlin);

    __nv_bfloat16 *xh, *xl, *ath, *atl;
    __nv_bfloat16 *wqh, *wql, *wkh, *wkl, *wvh, *wvl, *woh, *wol;
    __nv_bfloat16 *qh, *ql, *kh, *kl, *vth, *vtl;
    cudaGetSymbolAddress((void**)&xh,  g_xh);
    cudaGetSymbolAddress((void**)&xl,  g_xl);
    cudaGetSymbolAddress((void**)&ath, g_ath);
    cudaGetSymbolAddress((void**)&atl, g_atl);
    cudaGetSymbolAddress((void**)&wqh, g_wqt_h);
    cudaGetSymbolAddress((void**)&wql, g_wqt_l);
    cudaGetSymbolAddress((void**)&wkh, g_wkt_h);
    cudaGetSymbolAddress((void**)&wkl, g_wkt_l);
    cudaGetSymbolAddress((void**)&wvh, g_wvt_h);
    cudaGetSymbolAddress((void**)&wvl, g_wvt_l);
    cudaGetSymbolAddress((void**)&woh, g_wot_h);
    cudaGetSymbolAddress((void**)&wol, g_wot_l);
    cudaGetSymbolAddress((void**)&qh,  g_qh);
    cudaGetSymbolAddress((void**)&ql,  g_ql);
    cudaGetSymbolAddress((void**)&kh,  g_kh);
    cudaGetSymbolAddress((void**)&kl,  g_kl);
    cudaGetSymbolAddress((void**)&vth, g_vth);
    cudaGetSymbolAddress((void**)&vtl, g_vtl);

    const int M = B_ * L_;  // 2048

    cudaFuncSetAttribute(gemm_mma_kernel,
                         cudaFuncAttributeMaxDynamicSharedMemorySize, GEMM_SMEM_BYTES);
    cudaFuncSetAttribute(attn_mma_kernel,
                         cudaFuncAttributeMaxDynamicSharedMemorySize, ATTN_SMEM);

    // ---- operand prep ----
    convert_split_kernel<<<(M * HID_) / (256 * 4), 256>>>(x, xh, xl, M * HID_);
    transpose_split_kernel<<<dim3((NH_ * D_) / 32, HID_ / 32), dim3(32, 8)>>>(
        Wq, wqh, wql, HID_, NH_ * D_);
    transpose_split_kernel<<<dim3((NKV_ * D_) / 32, HID_ / 32), dim3(32, 8)>>>(
        Wk, wkh, wkl, HID_, NKV_ * D_);
    transpose_split_kernel<<<dim3((NKV_ * D_) / 32, HID_ / 32), dim3(32, 8)>>>(
        Wv, wvh, wvl, HID_, NKV_ * D_);
    transpose_split_kernel<<<dim3(HID_ / 32, (NH_ * D_) / 32), dim3(32, 8)>>>(
        Wo, woh, wol, NH_ * D_, HID_);

    // ---- QKV projections ----
    gemm_mma_kernel<<<dim3((NH_ * D_) / 128, M / 128), 256, GEMM_SMEM_BYTES>>>(
        xh, xl, wqh, wql, bq, qlin, NH_ * D_, HID_);
    gemm_mma_kernel<<<dim3((NKV_ * D_) / 128, M / 128), 256, GEMM_SMEM_BYTES>>>(
        xh, xl, wkh, wkl, bk, klin, NKV_ * D_, HID_);
    gemm_mma_kernel<<<dim3((NKV_ * D_) / 128, M / 128), 256, GEMM_SMEM_BYTES>>>(
        xh, xl, wvh, wvl, bv, vlin, NKV_ * D_, HID_);

    // ---- RoPE + cache assembly (split bf16 outputs) ----
    rope_q_kernel<<<(B_ * L_ * NH_ * D_) / 256, 256>>>(qlin, cosb, sinb, qh, ql);
    rope_k_kernel<<<(B_ * L_ * NKV_ * D_) / 256, 256>>>(klin, cosb, sinb, kh, kl);
    copy_past_k_kernel<<<(B_ * NKV_ * P_ * D_) / 256, 256>>>(past_k, kh, kl);
    transpose_v_new_kernel<<<dim3(D_ / 32, L_ / 32, B_ * NKV_), dim3(32, 8)>>>(
        vlin, vth, vtl);
    transpose_v_past_kernel<<<dim3(D_ / 32, P_ / 32, B_ * NKV_), dim3(32, 8)>>>(
        past_v, vth, vtl);

    // ---- Attention (tensor cores) ----
    attn_mma_kernel<<<dim3(L_ / 128, NH_, B_), 256, ATTN_SMEM>>>(
        qh, ql, kh, kl, vth, vtl, ath, atl);

    // ---- Output projection ----
    gemm_mma_kernel<<<dim3(HID_ / 128, M / 128), 256, GEMM_SMEM_BYTES>>>(
        ath, atl, woh, wol, nullptr, out, HID_, HID_);
}

// round 9
// speedup vs baseline: 2.7792x; 1.1007x over previous
#include <cuda_runtime.h>
#include <cuda_bf16.h>
#include <cstdint>

// ===========================================================================
// Problem constants
// ===========================================================================
#define B_    2
#define L_    1024
#define P_    1024
#define T_    2048
#define HID_  2048
#define NH_   32
#define NKV_  8
#define D_    64
#define SCALE_ 0.125f
#define QKVW  3072   // fused QKV output width (2048 + 512 + 512)

// ===========================================================================
// PTX helpers (baseline ISA only — tcgen05 unavailable on this PTX target)
// ===========================================================================
__device__ __forceinline__ uint32_t smem_to_u32(const void* smem_ptr) {
    uint32_t addr;
    asm("{ .reg .u64 tmp; cvta.to.shared.u64 tmp, %1; cvt.u32.u64 %0, tmp; }"
        : "=r"(addr) : "l"(smem_ptr));
    return addr;
}

__device__ __forceinline__ void ldsm_x4(uint32_t (&r)[4], uint32_t addr) {
    asm volatile("ldmatrix.sync.aligned.m8n8.x4.shared.b16 {%0,%1,%2,%3}, [%4];"
        : "=r"(r[0]), "=r"(r[1]), "=r"(r[2]), "=r"(r[3]) : "r"(addr));
}

__device__ __forceinline__ void mma_bf16(float (&d)[4], const uint32_t (&a)[4],
                                         uint32_t b0, uint32_t b1) {
    asm volatile(
        "mma.sync.aligned.m16n8k16.row.col.f32.bf16.bf16.f32 "
        "{%0,%1,%2,%3}, {%4,%5,%6,%7}, {%8,%9}, {%0,%1,%2,%3};"
        : "+f"(d[0]), "+f"(d[1]), "+f"(d[2]), "+f"(d[3])
        : "r"(a[0]), "r"(a[1]), "r"(a[2]), "r"(a[3]), "r"(b0), "r"(b1));
}

__device__ __forceinline__ void cp_async16(uint32_t saddr, const void* gaddr) {
    asm volatile("cp.async.cg.shared.global [%0], [%1], 16;"
        :: "r"(saddr), "l"(gaddr));
}
#define CP_COMMIT() asm volatile("cp.async.commit_group;" ::: "memory")
#define CP_WAIT2()  asm volatile("cp.async.wait_group 2;" ::: "memory")
#define CP_WAIT1()  asm volatile("cp.async.wait_group 1;" ::: "memory")
#define CP_WAIT0()  asm volatile("cp.async.wait_group 0;" ::: "memory")

// ===========================================================================
// Scratch (static device arrays; allocation is forbidden)
// ===========================================================================
__device__ float g_qkvlin[B_ * L_ * QKVW];            // fused QKV GEMM output

// split-bf16 operands
__device__ __nv_bfloat16 g_xh [B_ * L_ * HID_];
__device__ __nv_bfloat16 g_xl [B_ * L_ * HID_];
__device__ __nv_bfloat16 g_ath[B_ * L_ * NH_ * D_];   // attention out hi
__device__ __nv_bfloat16 g_atl[B_ * L_ * NH_ * D_];   // attention out lo
__device__ __nv_bfloat16 g_wcat_h[QKVW * HID_];       // [3072][2048] K-major
__device__ __nv_bfloat16 g_wcat_l[QKVW * HID_];
__device__ __nv_bfloat16 g_wot_h[HID_ * (NH_ * D_)];
__device__ __nv_bfloat16 g_wot_l[HID_ * (NH_ * D_)];
__device__ float         g_bcat[QKVW];

// attention operands (split bf16)
__device__ __nv_bfloat16 g_qh [B_ * NH_ * L_ * D_];   // (B,NH,L,D)
__device__ __nv_bfloat16 g_ql [B_ * NH_ * L_ * D_];
__device__ __nv_bfloat16 g_kh [B_ * NKV_ * T_ * D_];  // (B,NKV,T,D)
__device__ __nv_bfloat16 g_kl [B_ * NKV_ * T_ * D_];
__device__ __nv_bfloat16 g_vth[B_ * NKV_ * D_ * T_];  // (B,NKV,D,T)
__device__ __nv_bfloat16 g_vtl[B_ * NKV_ * D_ * T_];

__device__ __forceinline__ void split_bf16(float a, __nv_bfloat16& hi, __nv_bfloat16& lo)
{
    hi = __float2bfloat16_rn(a);
    lo = __float2bfloat16_rn(a - __bfloat162float(hi));
}

__device__ __forceinline__ void pack2_split(float x, float y, uint32_t& uh, uint32_t& ul)
{
    __nv_bfloat162 hb = __floats2bfloat162_rn(x, y);
    float lx = x - __bfloat162float(hb.x);
    float ly = y - __bfloat162float(hb.y);
    __nv_bfloat162 lb = __floats2bfloat162_rn(lx, ly);
    uh = *(uint32_t*)&hb;
    ul = *(uint32_t*)&lb;
}

// ===========================================================================
// Elementwise split conversion: A[n] fp32 -> H,L bf16
// ===========================================================================
__global__ void convert_split_kernel(const float* __restrict__ A,
                                     __nv_bfloat16* __restrict__ H,
                                     __nv_bfloat16* __restrict__ Lo, int n)
{
    int i = (blockIdx.x * blockDim.x + threadIdx.x) * 4;
    if (i >= n) return;
    float4 v = *(const float4*)(A + i);
    __nv_bfloat16 h0, l0, h1, l1, h2, l2, h3, l3;
    split_bf16(v.x, h0, l0);
    split_bf16(v.y, h1, l1);
    split_bf16(v.z, h2, l2);
    split_bf16(v.w, h3, l3);
    *(__nv_bfloat162*)(H + i)     = __nv_bfloat162(h0, h1);
    *(__nv_bfloat162*)(H + i + 2) = __nv_bfloat162(h2, h3);
    *(__nv_bfloat162*)(Lo + i)     = __nv_bfloat162(l0, l1);
    *(__nv_bfloat162*)(Lo + i + 2) = __nv_bfloat162(l2, l3);
}

// ===========================================================================
// Transpose + split: W[K,N] fp32 -> Th,Tl [N,K] bf16 (K-major)
// ===========================================================================
__global__ void transpose_split_kernel(const float* __restrict__ W,
                                       __nv_bfloat16* __restrict__ Th,
                                       __nv_bfloat16* __restrict__ Tl,
                                       int K, int N)
{
    __shared__ float t[32][33];
    int n0 = blockIdx.x * 32, k0 = blockIdx.y * 32;
    int tx = threadIdx.x, ty = threadIdx.y;   // 32 x 8
#pragma unroll
    for (int i = 0; i < 4; i++)
        t[ty + 8 * i][tx] = W[(size_t)(k0 + ty + 8 * i) * N + n0 + tx];
    __syncthreads();
#pragma unroll
    for (int i = 0; i < 4; i++) {
        float a = t[tx][ty + 8 * i];
        __nv_bfloat16 h, l;
        split_bf16(a, h, l);
        size_t o = (size_t)(n0 + ty + 8 * i) * K + k0 + tx;
        Th[o] = h;
        Tl[o] = l;
    }
}

// ===========================================================================
// Concatenate biases: [bq | bk | bv] -> g_bcat[3072]
// ===========================================================================
__global__ void concat_bias_kernel(const float* __restrict__ bq,
                                   const float* __restrict__ bk,
                                   const float* __restrict__ bv,
                                   float* __restrict__ out)
{
    int i = blockIdx.x * blockDim.x + threadIdx.x;
    if (i >= QKVW) return;
    out[i] = (i < 2048) ? bq[i] : (i < 2560) ? bk[i - 2048] : bv[i - 2560];
}

// ===========================================================================
// Split-bf16 mma.sync GEMM v2: C[M,N] = A[M,K] @ B[N,K]^T (+ bias)
// CTA tile 128(M) x 256(N), K-chunk 32, 3-stage cp.async pipeline.
// 8 warps: warp tile 64x64 (wm = wid&1, wn = wid>>1). 1 CTA/SM.
// Smem rows padded to 80B (ldmatrix conflict-free, verified R7).
// ===========================================================================
#define SROW_B   80
#define TILE_A2  (128 * SROW_B)              // 10240
#define TILE_B2  (256 * SROW_B)              // 20480
#define STAGE_B2 (2 * TILE_A2 + 2 * TILE_B2) // 61440
#define GEMM2_SMEM (3 * STAGE_B2)            // 184320

__global__ __launch_bounds__(256, 1) void gemm_mma2_kernel(
    const __nv_bfloat16* __restrict__ Ah, const __nv_bfloat16* __restrict__ Al,
    const __nv_bfloat16* __restrict__ Bh, const __nv_bfloat16* __restrict__ Bl,
    const float* __restrict__ bias, float* __restrict__ C, int N, int K)
{
    extern __shared__ char smem[];
    const uint32_t sb = smem_to_u32(smem);
    const int tid = threadIdx.x;
    const int lid = tid & 31;
    const int wid = tid >> 5;
    const int wm = wid & 1;          // M offset wm*64
    const int wn = wid >> 1;         // N offset wn*64
    const int bn = blockIdx.x * 256;
    const int bm = blockIdx.y * 128;

    const int arow = (lid & 7) + ((lid >> 3) & 1) * 8;
    const int akof = (lid >> 4) * 8;
    const int brow = (lid & 7) + (lid >> 4) * 8;
    const int bkof = ((lid >> 3) & 1) * 8;

    float acc[4][8][4];
#pragma unroll
    for (int mi = 0; mi < 4; mi++)
#pragma unroll
        for (int ni = 0; ni < 8; ni++)
#pragma unroll
            for (int u = 0; u < 4; u++) acc[mi][ni][u] = 0.f;

    const int nch = K >> 5;

    // ---- stage issue: A tiles 512 chunks each, B tiles 1024 chunks each
    auto issue_stage = [&](int ch, int stg) {
        const uint32_t db = sb + (uint32_t)(stg * STAGE_B2);
        const int k0 = ch << 5;
#pragma unroll
        for (int t = 0; t < 2; t++) {         // Ah, Al
            const __nv_bfloat16* g = t ? Al : Ah;
            const uint32_t so = db + t * TILE_A2;
#pragma unroll
            for (int i = 0; i < 2; i++) {
                int idx = tid + i * 256;      // < 512
                int r = idx >> 2, c = idx & 3;
                cp_async16(so + (uint32_t)(r * SROW_B + c * 16),
                           g + (size_t)(bm + r) * K + k0 + c * 8);
            }
        }
#pragma unroll
        for (int t = 0; t < 2; t++) {         // Bh, Bl
            const __nv_bfloat16* g = t ? Bl : Bh;
            const uint32_t so = db + 2 * TILE_A2 + t * TILE_B2;
#pragma unroll
            for (int i = 0; i < 4; i++) {
                int idx = tid + i * 256;      // < 1024
                int r = idx >> 2, c = idx & 3;
                cp_async16(so + (uint32_t)(r * SROW_B + c * 16),
                           g + (size_t)(bn + r) * K + k0 + c * 8);
            }
        }
        CP_COMMIT();
    };

    issue_stage(0, 0);
    if (nch > 1) issue_stage(1, 1);

    for (int ch = 0; ch < nch; ch++) {
        if (ch + 2 < nch) { issue_stage(ch + 2, (ch + 2) % 3); CP_WAIT2(); }
        else if (ch + 1 < nch) { CP_WAIT1(); }
        else { CP_WAIT0(); }
        __syncthreads();

        const uint32_t ub  = sb + (uint32_t)((ch % 3) * STAGE_B2);
        const uint32_t uAh = ub;
        const uint32_t uAl = ub + TILE_A2;
        const uint32_t uBh = ub + 2 * TILE_A2;
        const uint32_t uBl = ub + 2 * TILE_A2 + TILE_B2;

#pragma unroll
        for (int ks = 0; ks < 2; ks++) {
            uint32_t bhf[4][4], blf[4][4];
#pragma unroll
            for (int pr = 0; pr < 4; pr++) {
                uint32_t bo = (uint32_t)((wn * 64 + pr * 16 + brow) * SROW_B +
                                         (ks * 16 + bkof) * 2);
                ldsm_x4(bhf[pr], uBh + bo);
                ldsm_x4(blf[pr], uBl + bo);
            }
#pragma unroll
            for (int mi = 0; mi < 4; mi++) {
                uint32_t ahf[4], alf[4];
                uint32_t ao = (uint32_t)((wm * 64 + mi * 16 + arow) * SROW_B +
                                         (ks * 16 + akof) * 2);
                ldsm_x4(ahf, uAh + ao);
                ldsm_x4(alf, uAl + ao);
#pragma unroll
                for (int ni = 0; ni < 8; ni++) {
                    int pr = ni >> 1, s = (ni & 1) * 2;
                    mma_bf16(acc[mi][ni], ahf, bhf[pr][s], bhf[pr][s + 1]);
                    mma_bf16(acc[mi][ni], ahf, blf[pr][s], blf[pr][s + 1]);
                    mma_bf16(acc[mi][ni], alf, bhf[pr][s], bhf[pr][s + 1]);
                }
            }
        }
        __syncthreads();
    }

    // ---- epilogue
#pragma unroll
    for (int mi = 0; mi < 4; mi++) {
        int r0 = bm + wm * 64 + mi * 16 + (lid >> 2);
#pragma unroll
        for (int ni = 0; ni < 8; ni++) {
            int col = bn + wn * 64 + ni * 8 + (lid & 3) * 2;
            float b0 = 0.f, b1 = 0.f;
            if (bias) { b0 = bias[col]; b1 = bias[col + 1]; }
            float2 v0 = make_float2(acc[mi][ni][0] + b0, acc[mi][ni][1] + b1);
            float2 v1 = make_float2(acc[mi][ni][2] + b0, acc[mi][ni][3] + b1);
            *(float2*)(C + (size_t)r0 * N + col)       = v0;
            *(float2*)(C + (size_t)(r0 + 8) * N + col) = v1;
        }
    }
}

// ===========================================================================
// RoPE for Q: fused qkvlin (B,L,3072) cols [0,2048) -> split bf16 (B,NH,L,D)
// ===========================================================================
__global__ void rope_q_kernel(const float* __restrict__ qkv,
                              const float* __restrict__ cosb,
                              const float* __restrict__ sinb,
                              __nv_bfloat16* __restrict__ qh,
                              __nv_bfloat16* __restrict__ ql)
{
    int idx = blockIdx.x * blockDim.x + threadIdx.x;
    if (idx >= B_ * L_ * NH_ * D_) return;
    int d = idx & 63;
    int h = (idx >> 6) & 31;
    int l = (idx >> 11) & 1023;
    int b = idx >> 21;
    size_t rb = (size_t)(b * L_ + l) * QKVW + h * 64;
    float v  = qkv[rb + d];
    int  d2  = (d < 32) ? d + 32 : d - 32;
    float vp = qkv[rb + d2];
    float rot = (d < 32) ? -vp : vp;
    float o = v * cosb[l * 64 + d] + rot * sinb[l * 64 + d];
    __nv_bfloat16 hi, lo;
    split_bf16(o, hi, lo);
    size_t dst = (((size_t)(b * NH_ + h)) * L_ + l) * D_ + d;
    qh[dst] = hi;
    ql[dst] = lo;
}

// ===========================================================================
// RoPE for K: fused qkvlin cols [2048,2560) -> split bf16 cache at [P, T)
// ===========================================================================
__global__ void rope_k_kernel(const float* __restrict__ qkv,
                              const float* __restrict__ cosb,
                              const float* __restrict__ sinb,
                              __nv_bfloat16* __restrict__ kh,
                              __nv_bfloat16* __restrict__ kl)
{
    int idx = blockIdx.x * blockDim.x + threadIdx.x;
    if (idx >= B_ * L_ * NKV_ * D_) return;
    int d = idx & 63;
    int h = (idx >> 6) & 7;
    int l = (idx >> 9) & 1023;
    int b = idx >> 19;
    size_t rb = (size_t)(b * L_ + l) * QKVW + 2048 + h * 64;
    float v  = qkv[rb + d];
    int  d2  = (d < 32) ? d + 32 : d - 32;
    float vp = qkv[rb + d2];
    float rot = (d < 32) ? -vp : vp;
    float o = v * cosb[l * 64 + d] + rot * sinb[l * 64 + d];
    __nv_bfloat16 hi, lo;
    split_bf16(o, hi, lo);
    size_t dst = (((size_t)(b * NKV_ + h)) * T_ + (P_ + l)) * D_ + d;
    kh[dst] = hi;
    kl[dst] = lo;
}

// ===========================================================================
// Copy + split past K (B,NKV,P,D) into cache positions [0, P)
// ===========================================================================
__global__ void copy_past_k_kernel(const float* __restrict__ pk,
                                   __nv_bfloat16* __restrict__ kh,
                                   __nv_bfloat16* __restrict__ kl)
{
    int idx = blockIdx.x * blockDim.x + threadIdx.x;
    if (idx >= B_ * NKV_ * P_ * D_) return;
    int d = idx & 63;
    int t = (idx >> 6) & 1023;
    int h = (idx >> 16) & 7;
    int b = idx >> 19;
    __nv_bfloat16 hi, lo;
    split_bf16(pk[idx], hi, lo);
    size_t dst = (((size_t)(b * NKV_ + h)) * T_ + t) * D_ + d;
    kh[dst] = hi;
    kl[dst] = lo;
}

// ===========================================================================
// Transpose + split V (new): qkvlin cols [2560,3072) -> (B,NKV,D,T) at [P, T)
// grid (D/32, L/32, B*NKV), block (32, 8)
// ===========================================================================
__global__ void transpose_v_new_kernel(const float* __restrict__ qkv,
                                       __nv_bfloat16* __restrict__ vth,
                                       __nv_bfloat16* __restrict__ vtl)
{
    __shared__ float t[32][33];
    int bh = blockIdx.z;
    int b = bh >> 3, h = bh & 7;
    int l0 = blockIdx.y * 32, d0 = blockIdx.x * 32;
    int tx = threadIdx.x, ty = threadIdx.y;
#pragma unroll
    for (int i = 0; i < 4; i++)
        t[ty + 8 * i][tx] =
            qkv[(size_t)(b * L_ + l0 + ty + 8 * i) * QKVW + 2560 + h * 64 + d0 + tx];
    __syncthreads();
#pragma unroll
    for (int i = 0; i < 4; i++) {
        float a = t[tx][ty + 8 * i];
        __nv_bfloat16 hi, lo;
        split_bf16(a, hi, lo);
        size_t dst = (((size_t)(b * NKV_ + h)) * D_ + d0 + ty + 8 * i) * T_ +
                     P_ + l0 + tx;
        vth[dst] = hi;
        vtl[dst] = lo;
    }
}

// ===========================================================================
// Transpose + split V (past): past_v (B,NKV,P,D) -> (B,NKV,D,T) at [0, P)
// ===========================================================================
__global__ void transpose_v_past_kernel(const float* __restrict__ pv,
                                        __nv_bfloat16* __restrict__ vth,
                                        __nv_bfloat16* __restrict__ vtl)
{
    __shared__ float t[32][33];
    int bh = blockIdx.z;
    int l0 = blockIdx.y * 32, d0 = blockIdx.x * 32;
    int tx = threadIdx.x, ty = threadIdx.y;
#pragma unroll
    for (int i = 0; i < 4; i++)
        t[ty + 8 * i][tx] =
            pv[((size_t)bh * P_ + l0 + ty + 8 * i) * D_ + d0 + tx];
    __syncthreads();
#pragma unroll
    for (int i = 0; i < 4; i++) {
        float a = t[tx][ty + 8 * i];
        __nv_bfloat16 hi, lo;
        split_bf16(a, hi, lo);
        size_t dst = ((size_t)bh * D_ + d0 + ty + 8 * i) * T_ + l0 + tx;
        vth[dst] = hi;
        vtl[dst] = lo;
    }
}

// ===========================================================================
// Tensor-core flash attention (unchanged from R8; ~530 TF/s effective)
// ===========================================================================
#define VROW   72
#define QT_B   (128 * VROW * 2)
#define KT_B   (64 * VROW * 2)
#define KVBUF  (4 * KT_B)
#define ATTN_SMEM (2 * QT_B + 2 * KVBUF)

__global__ __launch_bounds__(256) void attn_mma_kernel(
    const __nv_bfloat16* __restrict__ Qh, const __nv_bfloat16* __restrict__ Ql,
    const __nv_bfloat16* __restrict__ Kh, const __nv_bfloat16* __restrict__ Kl,
    const __nv_bfloat16* __restrict__ Vth, const __nv_bfloat16* __restrict__ Vtl,
    __nv_bfloat16* __restrict__ Oh, __nv_bfloat16* __restrict__ Ol)
{
    extern __shared__ char smem[];
    const uint32_t sb = smem_to_u32(smem);
    const uint32_t sQh = sb;
    const uint32_t sQl = sb + QT_B;
    const uint32_t sKV = sb + 2 * QT_B;

    const int tid = threadIdx.x;
    const int lid = tid & 31;
    const int wid = tid >> 5;
    const int qb  = (L_ / 128 - 1) - blockIdx.x;
    const int h   = blockIdx.y;
    const int b   = blockIdx.z;
    const int hk  = h >> 2;
    const int q0  = qb * 128;
    const int ntiles = (P_ + q0 + 128) / 64;

    const int arow = (lid & 7) + ((lid >> 3) & 1) * 8;
    const int akof = (lid >> 4) * 8;
    const int brow = (lid & 7) + (lid >> 4) * 8;
    const int bkof = ((lid >> 3) & 1) * 8;

    const __nv_bfloat16* qh_base = Qh + ((size_t)(b * NH_ + h) * L_ + q0) * D_;
    const __nv_bfloat16* ql_base = Ql + ((size_t)(b * NH_ + h) * L_ + q0) * D_;
    const __nv_bfloat16* kh_base = Kh + (size_t)(b * NKV_ + hk) * T_ * D_;
    const __nv_bfloat16* kl_base = Kl + (size_t)(b * NKV_ + hk) * T_ * D_;
    const __nv_bfloat16* vh_base = Vth + (size_t)(b * NKV_ + hk) * D_ * T_;
    const __nv_bfloat16* vl_base = Vtl + (size_t)(b * NKV_ + hk) * D_ * T_;

    const int ltile = tid >> 6;
    const int lsub  = tid & 63;
    const __nv_bfloat16* kvg =
        (ltile == 0) ? kh_base : (ltile == 1) ? kl_base :
        (ltile == 2) ? vh_base : vl_base;
    const bool isV = (ltile >= 2);
    const uint32_t kvs_off = (uint32_t)(ltile * KT_B);

    {
        const uint32_t db = sKV + kvs_off;
#pragma unroll
        for (int i = 0; i < 8; i++) {
            int chunk = lsub + i * 64;
            int r = chunk >> 3, c = chunk & 7;
            const __nv_bfloat16* src = isV
                ? kvg + (size_t)r * T_ + c * 8
                : kvg + (size_t)r * D_ + c * 8;
            cp_async16(db + (uint32_t)(r * 144 + c * 16), src);
        }
        CP_COMMIT();
    }

#pragma unroll
    for (int t = 0; t < 2; t++) {
        const __nv_bfloat16* src = t ? ql_base : qh_base;
        const uint32_t dstb = t ? sQl : sQh;
#pragma unroll
        for (int i = 0; i < 4; i++) {
            int chunk = tid + i * 256;
            int r = chunk >> 3, c = chunk & 7;
            uint4 v = *(const uint4*)(src + (size_t)r * D_ + c * 8);
            *(uint4*)(smem + (dstb - sb) + r * 144 + c * 16) = v;
        }
    }

    float o[8][4];
#pragma unroll
    for (int ni = 0; ni < 8; ni++)
#pragma unroll
        for (int u = 0; u < 4; u++) o[ni][u] = 0.f;
    float m1 = -1e30f, m2 = -1e30f, l1 = 0.f, l2 = 0.f;

    const int qi1 = q0 + wid * 16 + (lid >> 2);
    const int qi2 = qi1 + 8;
    const int lim1 = qi1 + P_;
    const int lim2 = qi2 + P_;

    for (int kt = 0; kt < ntiles; kt++) {
        if (kt + 1 < ntiles) {
            const uint32_t db = sKV + ((kt + 1) & 1) * KVBUF + kvs_off;
            const int t0 = (kt + 1) * 64;
#pragma unroll
            for (int i = 0; i < 8; i++) {
                int chunk = lsub + i * 64;
                int r = chunk >> 3, c = chunk & 7;
                const __nv_bfloat16* src = isV
                    ? kvg + (size_t)r * T_ + t0 + c * 8
                    : kvg + (size_t)(t0 + r) * D_ + c * 8;
                cp_async16(db + (uint32_t)(r * 144 + c * 16), src);
            }
            CP_COMMIT();
            CP_WAIT1();
        } else {
            CP_WAIT0();
        }
        __syncthreads();

        const uint32_t ub  = sKV + (kt & 1) * KVBUF;
        const uint32_t uKh = ub;
        const uint32_t uKl = ub + KT_B;
        const uint32_t uVh = ub + 2 * KT_B;
        const uint32_t uVl = ub + 3 * KT_B;

        float s[8][4];
#pragma unroll
        for (int ni = 0; ni < 8; ni++)
#pragma unroll
            for (int u = 0; u < 4; u++) s[ni][u] = 0.f;

#pragma unroll
        for (int ks = 0; ks < 4; ks++) {
            uint32_t ahf[4], alf[4];
            uint32_t ao = (uint32_t)((wid * 16 + arow) * 144 + (ks * 16 + akof) * 2);
            ldsm_x4(ahf, sQh + ao);
            ldsm_x4(alf, sQl + ao);
#pragma unroll
            for (int pr = 0; pr < 4; pr++) {
                uint32_t bhf[4], blf[4];
                uint32_t bo = (uint32_t)((pr * 16 + brow) * 144 + (ks * 16 + bkof) * 2);
                ldsm_x4(bhf, uKh + bo);
                ldsm_x4(blf, uKl + bo);
#pragma unroll
                for (int t = 0; t < 2; t++) {
                    int ni = 2 * pr + t, s2 = t * 2;
                    mma_bf16(s[ni], ahf, bhf[s2], bhf[s2 + 1]);
                    mma_bf16(s[ni], ahf, blf[s2], blf[s2 + 1]);
                    mma_bf16(s[ni], alf, bhf[s2], bhf[s2 + 1]);
                }
            }
        }

#pragma unroll
        for (int ni = 0; ni < 8; ni++)
#pragma unroll
            for (int u = 0; u < 4; u++) s[ni][u] *= SCALE_;

        if (kt >= ntiles - 2) {
            int jc = kt * 64 + 2 * (lid & 3);
#pragma unroll
            for (int ni = 0; ni < 8; ni++) {
                int j = jc + 8 * ni;
                if (j     > lim1) s[ni][0] = -1e30f;
                if (j + 1 > lim1) s[ni][1] = -1e30f;
                if (j     > lim2) s[ni][2] = -1e30f;
                if (j + 1 > lim2) s[ni][3] = -1e30f;
            }
        }

        float mx1 = -1e30f, mx2 = -1e30f;
#pragma unroll
        for (int ni = 0; ni < 8; ni++) {
            mx1 = fmaxf(mx1, fmaxf(s[ni][0], s[ni][1]));
            mx2 = fmaxf(mx2, fmaxf(s[ni][2], s[ni][3]));
        }
        mx1 = fmaxf(mx1, __shfl_xor_sync(0xffffffffu, mx1, 1));
        mx1 = fmaxf(mx1, __shfl_xor_sync(0xffffffffu, mx1, 2));
        mx2 = fmaxf(mx2, __shfl_xor_sync(0xffffffffu, mx2, 1));
        mx2 = fmaxf(mx2, __shfl_xor_sync(0xffffffffu, mx2, 2));

        float mn1 = fmaxf(m1, mx1), mn2 = fmaxf(m2, mx2);
        float c1 = __expf(m1 - mn1), c2 = __expf(m2 - mn2);
        m1 = mn1; m2 = mn2;

        float p1 = 0.f, p2 = 0.f;
#pragma unroll
        for (int ni = 0; ni < 8; ni++) {
            s[ni][0] = __expf(s[ni][0] - mn1);
            s[ni][1] = __expf(s[ni][1] - mn1);
            s[ni][2] = __expf(s[ni][2] - mn2);
            s[ni][3] = __expf(s[ni][3] - mn2);
            p1 += s[ni][0] + s[ni][1];
            p2 += s[ni][2] + s[ni][3];
        }
        p1 += __shfl_xor_sync(0xffffffffu, p1, 1);
        p1 += __shfl_xor_sync(0xffffffffu, p1, 2);
        p2 += __shfl_xor_sync(0xffffffffu, p2, 1);
        p2 += __shfl_xor_sync(0xffffffffu, p2, 2);
        l1 = l1 * c1 + p1;
        l2 = l2 * c2 + p2;

#pragma unroll
        for (int ni = 0; ni < 8; ni++) {
            o[ni][0] *= c1; o[ni][1] *= c1;
            o[ni][2] *= c2; o[ni][3] *= c2;
        }

#pragma unroll
        for (int ks = 0; ks < 4; ks++) {
            uint32_t aPh[4], aPl[4];
            pack2_split(s[2 * ks][0],     s[2 * ks][1],     aPh[0], aPl[0]);
            pack2_split(s[2 * ks][2],     s[2 * ks][3],     aPh[1], aPl[1]);
            pack2_split(s[2 * ks + 1][0], s[2 * ks + 1][1], aPh[2], aPl[2]);
            pack2_split(s[2 * ks + 1][2], s[2 * ks + 1][3], aPh[3], aPl[3]);
#pragma unroll
            for (int pr = 0; pr < 4; pr++) {
                uint32_t bvh[4], bvl[4];
                uint32_t bo = (uint32_t)((pr * 16 + brow) * 144 + (ks * 16 + bkof) * 2);
                ldsm_x4(bvh, uVh + bo);
                ldsm_x4(bvl, uVl + bo);
#pragma unroll
                for (int t = 0; t < 2; t++) {
                    int ni = 2 * pr + t, s2 = t * 2;
                    mma_bf16(o[ni], aPh, bvh[s2], bvh[s2 + 1]);
                    mma_bf16(o[ni], aPh, bvl[s2], bvl[s2 + 1]);
                    mma_bf16(o[ni], aPl, bvh[s2], bvh[s2 + 1]);
                }
            }
        }
        __syncthreads();
    }

    float inv1 = 1.f / l1, inv2 = 1.f / l2;
    size_t base1 = (((size_t)b * L_ + qi1) * NH_ + h) * D_;
    size_t base2 = (((size_t)b * L_ + qi2) * NH_ + h) * D_;
#pragma unroll
    for (int ni = 0; ni < 8; ni++) {
        int d = 8 * ni + 2 * (lid & 3);
        uint32_t uh, ul;
        pack2_split(o[ni][0] * inv1, o[ni][1] * inv1, uh, ul);
        *(uint32_t*)(Oh + base1 + d) = uh;
        *(uint32_t*)(Ol + base1 + d) = ul;
        pack2_split(o[ni][2] * inv2, o[ni][3] * inv2, uh, ul);
        *(uint32_t*)(Oh + base2 + d) = uh;
        *(uint32_t*)(Ol + base2 + d) = ul;
    }
}

// ===========================================================================
// Launch
// ===========================================================================
extern "C" void kernel_launch(void* const* d_in, const int* in_sizes, int n_in,
                              void* d_out, int out_size)
{
    const float* x      = (const float*)d_in[0];
    const float* cosb   = (const float*)d_in[2];
    const float* sinb   = (const float*)d_in[3];
    const float* past_k = (const float*)d_in[4];
    const float* past_v = (const float*)d_in[5];
    const float* Wq     = (const float*)d_in[6];
    const float* bq     = (const float*)d_in[7];
    const float* Wk     = (const float*)d_in[8];
    const float* bk     = (const float*)d_in[9];
    const float* Wv     = (const float*)d_in[10];
    const float* bv     = (const float*)d_in[11];
    const float* Wo     = (const float*)d_in[12];
    float* out          = (float*)d_out;

    float *qkvlin, *bcat;
    cudaGetSymbolAddress((void**)&qkvlin, g_qkvlin);
    cudaGetSymbolAddress((void**)&bcat,   g_bcat);

    __nv_bfloat16 *xh, *xl, *ath, *atl;
    __nv_bfloat16 *wch, *wcl, *woh, *wol;
    __nv_bfloat16 *qh, *ql, *kh, *kl, *vth, *vtl;
    cudaGetSymbolAddress((void**)&xh,  g_xh);
    cudaGetSymbolAddress((void**)&xl,  g_xl);
    cudaGetSymbolAddress((void**)&ath, g_ath);
    cudaGetSymbolAddress((void**)&atl, g_atl);
    cudaGetSymbolAddress((void**)&wch, g_wcat_h);
    cudaGetSymbolAddress((void**)&wcl, g_wcat_l);
    cudaGetSymbolAddress((void**)&woh, g_wot_h);
    cudaGetSymbolAddress((void**)&wol, g_wot_l);
    cudaGetSymbolAddress((void**)&qh,  g_qh);
    cudaGetSymbolAddress((void**)&ql,  g_ql);
    cudaGetSymbolAddress((void**)&kh,  g_kh);
    cudaGetSymbolAddress((void**)&kl,  g_kl);
    cudaGetSymbolAddress((void**)&vth, g_vth);
    cudaGetSymbolAddress((void**)&vtl, g_vtl);

    const int M = B_ * L_;  // 2048

    cudaFuncSetAttribute(gemm_mma2_kernel,
                         cudaFuncAttributeMaxDynamicSharedMemorySize, GEMM2_SMEM);
    cudaFuncSetAttribute(attn_mma_kernel,
                         cudaFuncAttributeMaxDynamicSharedMemorySize, ATTN_SMEM);

    // ---- operand prep ----
    convert_split_kernel<<<(M * HID_) / (256 * 4), 256>>>(x, xh, xl, M * HID_);
    // Wq -> wcat rows [0,2048), Wk -> [2048,2560), Wv -> [2560,3072)
    transpose_split_kernel<<<dim3(HID_ / 32, HID_ / 32), dim3(32, 8)>>>(
        Wq, wch, wcl, HID_, HID_);
    transpose_split_kernel<<<dim3((NKV_ * D_) / 32, HID_ / 32), dim3(32, 8)>>>(
        Wk, wch + (size_t)2048 * HID_, wcl + (size_t)2048 * HID_, HID_, NKV_ * D_);
    transpose_split_kernel<<<dim3((NKV_ * D_) / 32, HID_ / 32), dim3(32, 8)>>>(
        Wv, wch + (size_t)2560 * HID_, wcl + (size_t)2560 * HID_, HID_, NKV_ * D_);
    transpose_split_kernel<<<dim3(HID_ / 32, (NH_ * D_) / 32), dim3(32, 8)>>>(
        Wo, woh, wol, NH_ * D_, HID_);
    concat_bias_kernel<<<QKVW / 256, 256>>>(bq, bk, bv, bcat);

    // ---- fused QKV projection: [M, 3072] ----
    gemm_mma2_kernel<<<dim3(QKVW / 256, M / 128), 256, GEMM2_SMEM>>>(
        xh, xl, wch, wcl, bcat, qkvlin, QKVW, HID_);

    // ---- RoPE + cache assembly (split bf16 outputs) ----
    rope_q_kernel<<<(B_ * L_ * NH_ * D_) / 256, 256>>>(qkvlin, cosb, sinb, qh, ql);
    rope_k_kernel<<<(B_ * L_ * NKV_ * D_) / 256, 256>>>(qkvlin, cosb, sinb, kh, kl);
    copy_past_k_kernel<<<(B_ * NKV_ * P_ * D_) / 256, 256>>>(past_k, kh, kl);
    transpose_v_new_kernel<<<dim3(D_ / 32, L_ / 32, B_ * NKV_), dim3(32, 8)>>>(
        qkvlin, vth, vtl);
    transpose_v_past_kernel<<<dim3(D_ / 32, P_ / 32, B_ * NKV_), dim3(32, 8)>>>(
        past_v, vth, vtl);

    // ---- Attention (tensor cores) ----
    attn_mma_kernel<<<dim3(L_ / 128, NH_, B_), 256, ATTN_SMEM>>>(
        qh, ql, kh, kl, vth, vtl, ath, atl);

    // ---- Output projection ----
    gemm_mma2_kernel<<<dim3(HID_ / 256, M / 128), 256, GEMM2_SMEM>>>(
        ath, atl, woh, wol, nullptr, out, HID_, HID_);
}

// round 11
// speedup vs baseline: 2.8479x; 1.0247x over previous
#include <cuda_runtime.h>
#include <cuda_bf16.h>
#include <cstdint>

// ===========================================================================
// Problem constants
// ===========================================================================
#define B_    2
#define L_    1024
#define P_    1024
#define T_    2048
#define HID_  2048
#define NH_   32
#define NKV_  8
#define D_    64
#define SCALE_ 0.125f
#define QKVW  3072

// ===========================================================================
// PTX helpers
// ===========================================================================
__device__ __forceinline__ uint32_t smem_to_u32(const void* smem_ptr) {
    uint32_t addr;
    asm("{ .reg .u64 tmp; cvta.to.shared.u64 tmp, %1; cvt.u32.u64 %0, tmp; }"
        : "=r"(addr) : "l"(smem_ptr));
    return addr;
}

__device__ __forceinline__ void ldsm_x4(uint32_t (&r)[4], uint32_t addr) {
    asm volatile("ldmatrix.sync.aligned.m8n8.x4.shared.b16 {%0,%1,%2,%3}, [%4];"
        : "=r"(r[0]), "=r"(r[1]), "=r"(r[2]), "=r"(r[3]) : "r"(addr));
}

__device__ __forceinline__ void mma_bf16(float (&d)[4], const uint32_t (&a)[4],
                                         uint32_t b0, uint32_t b1) {
    asm volatile(
        "mma.sync.aligned.m16n8k16.row.col.f32.bf16.bf16.f32 "
        "{%0,%1,%2,%3}, {%4,%5,%6,%7}, {%8,%9}, {%0,%1,%2,%3};"
        : "+f"(d[0]), "+f"(d[1]), "+f"(d[2]), "+f"(d[3])
        : "r"(a[0]), "r"(a[1]), "r"(a[2]), "r"(a[3]), "r"(b0), "r"(b1));
}

__device__ __forceinline__ void cp_async16(uint32_t saddr, const void* gaddr) {
    asm volatile("cp.async.cg.shared.global [%0], [%1], 16;"
        :: "r"(saddr), "l"(gaddr));
}
#define CP_COMMIT() asm volatile("cp.async.commit_group;" ::: "memory")
#define CP_WAIT2()  asm volatile("cp.async.wait_group 2;" ::: "memory")
#define CP_WAIT1()  asm volatile("cp.async.wait_group 1;" ::: "memory")
#define CP_WAIT0()  asm volatile("cp.async.wait_group 0;" ::: "memory")

// ===========================================================================
// Scratch
// ===========================================================================
__device__ float g_qkvlin[B_ * L_ * QKVW];

__device__ __nv_bfloat16 g_xh [B_ * L_ * HID_];
__device__ __nv_bfloat16 g_xl [B_ * L_ * HID_];
__device__ __nv_bfloat16 g_ath[B_ * L_ * NH_ * D_];
__device__ __nv_bfloat16 g_atl[B_ * L_ * NH_ * D_];
__device__ __nv_bfloat16 g_wcat_h[QKVW * HID_];
__device__ __nv_bfloat16 g_wcat_l[QKVW * HID_];
__device__ __nv_bfloat16 g_wot_h[HID_ * (NH_ * D_)];
__device__ __nv_bfloat16 g_wot_l[HID_ * (NH_ * D_)];
__device__ float         g_bcat[QKVW];

__device__ __nv_bfloat16 g_qh [B_ * NH_ * L_ * D_];
__device__ __nv_bfloat16 g_ql [B_ * NH_ * L_ * D_];
__device__ __nv_bfloat16 g_kh [B_ * NKV_ * T_ * D_];
__device__ __nv_bfloat16 g_kl [B_ * NKV_ * T_ * D_];
__device__ __nv_bfloat16 g_vth[B_ * NKV_ * D_ * T_];
__device__ __nv_bfloat16 g_vtl[B_ * NKV_ * D_ * T_];

__device__ __forceinline__ void split_bf16(float a, __nv_bfloat16& hi, __nv_bfloat16& lo)
{
    hi = __float2bfloat16_rn(a);
    lo = __float2bfloat16_rn(a - __bfloat162float(hi));
}

__device__ __forceinline__ void pack2_split(float x, float y, uint32_t& uh, uint32_t& ul)
{
    __nv_bfloat162 hb = __floats2bfloat162_rn(x, y);
    float lx = x - __bfloat162float(hb.x);
    float ly = y - __bfloat162float(hb.y);
    __nv_bfloat162 lb = __floats2bfloat162_rn(lx, ly);
    uh = *(uint32_t*)&hb;
    ul = *(uint32_t*)&lb;
}

// ===========================================================================
// Merged prep kernel: weight transposes + x split + bias concat.
// Flat grid of 14348 blocks, 256 threads. Segments:
//  [0,4096)      Wq  transpose  -> wcat rows [0,2048)
//  [4096,5120)   Wk  transpose  -> wcat rows [2048,2560)
//  [5120,6144)   Wv  transpose  -> wcat rows [2560,3072)
//  [6144,10240)  Wo  transpose  -> wot
//  [10240,14336) x   split-convert
//  [14336,14348) bias concat
// ===========================================================================
__device__ __forceinline__ void transpose_seg(
    const float* __restrict__ W, __nv_bfloat16* __restrict__ Th,
    __nv_bfloat16* __restrict__ Tl, int K, int N, int n0, int k0,
    int tx, int ty, float (*t)[33])
{
#pragma unroll
    for (int i = 0; i < 4; i++)
        t[ty + 8 * i][tx] = W[(size_t)(k0 + ty + 8 * i) * N + n0 + tx];
    __syncthreads();
#pragma unroll
    for (int i = 0; i < 4; i++) {
        float a = t[tx][ty + 8 * i];
        __nv_bfloat16 h, l;
        split_bf16(a, h, l);
        size_t o = (size_t)(n0 + ty + 8 * i) * K + k0 + tx;
        Th[o] = h;
        Tl[o] = l;
    }
}

__global__ void prep_w_kernel(
    const float* __restrict__ Wq, const float* __restrict__ Wk,
    const float* __restrict__ Wv, const float* __restrict__ Wo,
    const float* __restrict__ bq, const float* __restrict__ bk,
    const float* __restrict__ bv, const float* __restrict__ x,
    __nv_bfloat16* __restrict__ wch, __nv_bfloat16* __restrict__ wcl,
    __nv_bfloat16* __restrict__ woh, __nv_bfloat16* __restrict__ wol,
    float* __restrict__ bcat,
    __nv_bfloat16* __restrict__ xh, __nv_bfloat16* __restrict__ xl)
{
    __shared__ float t[32][33];
    const int bid = blockIdx.x;
    const int tid = threadIdx.x;
    const int tx = tid & 31, ty = tid >> 5;

    if (bid < 4096) {                     // Wq: N=2048
        int lb = bid;
        transpose_seg(Wq, wch, wcl, HID_, 2048,
                      (lb & 63) * 32, (lb >> 6) * 32, tx, ty, t);
    } else if (bid < 5120) {              // Wk: N=512 -> rows 2048+
        int lb = bid - 4096;
        transpose_seg(Wk, wch + (size_t)2048 * HID_, wcl + (size_t)2048 * HID_,
                      HID_, 512, (lb & 15) * 32, (lb >> 4) * 32, tx, ty, t);
    } else if (bid < 6144) {              // Wv: N=512 -> rows 2560+
        int lb = bid - 5120;
        transpose_seg(Wv, wch + (size_t)2560 * HID_, wcl + (size_t)2560 * HID_,
                      HID_, 512, (lb & 15) * 32, (lb >> 4) * 32, tx, ty, t);
    } else if (bid < 10240) {             // Wo: [2048,2048]
        int lb = bid - 6144;
        transpose_seg(Wo, woh, wol, NH_ * D_, HID_,
                      (lb & 63) * 32, (lb >> 6) * 32, tx, ty, t);
    } else if (bid < 14336) {             // x split: 4 elems/thread
        int i = ((bid - 10240) * 256 + tid) * 4;
        float4 v = *(const float4*)(x + i);
        __nv_bfloat16 h0, l0, h1, l1, h2, l2, h3, l3;
        split_bf16(v.x, h0, l0);
        split_bf16(v.y, h1, l1);
        split_bf16(v.z, h2, l2);
        split_bf16(v.w, h3, l3);
        *(__nv_bfloat162*)(xh + i)     = __nv_bfloat162(h0, h1);
        *(__nv_bfloat162*)(xh + i + 2) = __nv_bfloat162(h2, h3);
        *(__nv_bfloat162*)(xl + i)     = __nv_bfloat162(l0, l1);
        *(__nv_bfloat162*)(xl + i + 2) = __nv_bfloat162(l2, l3);
    } else {                              // bias concat
        int i = (bid - 14336) * 256 + tid;
        if (i < QKVW)
            bcat[i] = (i < 2048) ? bq[i] : (i < 2560) ? bk[i - 2048] : bv[i - 2560];
    }
}

// ===========================================================================
// Split-bf16 mma.sync GEMM v3: 128x128 CTA, K-chunk 32, 3-stage pipeline.
// 8 warps: warp tile 32(M) x 64(N). acc = 64 regs/thread.
// ===========================================================================
#define SROW_B   80
#define TILE_B3  (128 * SROW_B)             // 10240
#define STAGE_B3 (4 * TILE_B3)              // 40960 (Ah, Al, Bh, Bl)
#define GEMM3_SMEM (3 * STAGE_B3)           // 122880

__global__ __launch_bounds__(256) void gemm_mma3_kernel(
    const __nv_bfloat16* __restrict__ Ah, const __nv_bfloat16* __restrict__ Al,
    const __nv_bfloat16* __restrict__ Bh, const __nv_bfloat16* __restrict__ Bl,
    const float* __restrict__ bias, float* __restrict__ C, int N, int K)
{
    extern __shared__ char smem[];
    const uint32_t sb = smem_to_u32(smem);
    const int tid = threadIdx.x;
    const int lid = tid & 31;
    const int wid = tid >> 5;
    const int wm = wid & 3;
    const int wn = wid >> 2;
    const int bn = blockIdx.x * 128;
    const int bm = blockIdx.y * 128;

    const int ltile = tid >> 6;                  // 0:Ah 1:Al 2:Bh 3:Bl
    const int lsub  = tid & 63;
    const __nv_bfloat16* gbase =
        (ltile == 0) ? Ah : (ltile == 1) ? Al : (ltile == 2) ? Bh : Bl;
    const int rowbase = (ltile < 2) ? bm : bn;
    const uint32_t stile_off = (uint32_t)(ltile * TILE_B3);

    const int arow = (lid & 7) + ((lid >> 3) & 1) * 8;
    const int akof = (lid >> 4) * 8;
    const int brow = (lid & 7) + (lid >> 4) * 8;
    const int bkof = ((lid >> 3) & 1) * 8;

    float acc[2][8][4];
#pragma unroll
    for (int mi = 0; mi < 2; mi++)
#pragma unroll
        for (int ni = 0; ni < 8; ni++)
#pragma unroll
            for (int u = 0; u < 4; u++) acc[mi][ni][u] = 0.f;

    const int nch = K >> 5;

    auto issue_stage = [&](int ch, int stg) {
        const uint32_t db = sb + (uint32_t)(stg * STAGE_B3) + stile_off;
        const int k0 = ch << 5;
#pragma unroll
        for (int i = 0; i < 8; i++) {
            int idx = lsub + i * 64;
            int r = idx >> 2, c = idx & 3;
            cp_async16(db + (uint32_t)(r * SROW_B + c * 16),
                       gbase + (size_t)(rowbase + r) * K + k0 + c * 8);
        }
        CP_COMMIT();
    };

    issue_stage(0, 0);
    if (nch > 1) issue_stage(1, 1);

    for (int ch = 0; ch < nch; ch++) {
        if (ch + 2 < nch) { issue_stage(ch + 2, (ch + 2) % 3); CP_WAIT2(); }
        else if (ch + 1 < nch) { CP_WAIT1(); }
        else { CP_WAIT0(); }
        __syncthreads();

        const uint32_t ub  = sb + (uint32_t)((ch % 3) * STAGE_B3);
        const uint32_t uAh = ub;
        const uint32_t uAl = ub + TILE_B3;
        const uint32_t uBh = ub + 2 * TILE_B3;
        const uint32_t uBl = ub + 3 * TILE_B3;

#pragma unroll
        for (int ks = 0; ks < 2; ks++) {
            uint32_t ahf[2][4], alf[2][4], bhf[4][4], blf[4][4];
#pragma unroll
            for (int mi = 0; mi < 2; mi++) {
                uint32_t ao = (uint32_t)((wm * 32 + mi * 16 + arow) * SROW_B +
                                         (ks * 16 + akof) * 2);
                ldsm_x4(ahf[mi], uAh + ao);
                ldsm_x4(alf[mi], uAl + ao);
            }
#pragma unroll
            for (int pr = 0; pr < 4; pr++) {
                uint32_t bo = (uint32_t)((wn * 64 + pr * 16 + brow) * SROW_B +
                                         (ks * 16 + bkof) * 2);
                ldsm_x4(bhf[pr], uBh + bo);
                ldsm_x4(blf[pr], uBl + bo);
            }
#pragma unroll
            for (int mi = 0; mi < 2; mi++)
#pragma unroll
                for (int ni = 0; ni < 8; ni++) {
                    int pr = ni >> 1, s = (ni & 1) * 2;
                    mma_bf16(acc[mi][ni], ahf[mi], bhf[pr][s], bhf[pr][s + 1]);
                    mma_bf16(acc[mi][ni], ahf[mi], blf[pr][s], blf[pr][s + 1]);
                    mma_bf16(acc[mi][ni], alf[mi], bhf[pr][s], bhf[pr][s + 1]);
                }
        }
        __syncthreads();
    }

#pragma unroll
    for (int mi = 0; mi < 2; mi++) {
        int r0 = bm + wm * 32 + mi * 16 + (lid >> 2);
#pragma unroll
        for (int ni = 0; ni < 8; ni++) {
            int col = bn + wn * 64 + ni * 8 + (lid & 3) * 2;
            float b0 = 0.f, b1 = 0.f;
            if (bias) { b0 = bias[col]; b1 = bias[col + 1]; }
            float2 v0 = make_float2(acc[mi][ni][0] + b0, acc[mi][ni][1] + b1);
            float2 v1 = make_float2(acc[mi][ni][2] + b0, acc[mi][ni][3] + b1);
            *(float2*)(C + (size_t)r0 * N + col)       = v0;
            *(float2*)(C + (size_t)(r0 + 8) * N + col) = v1;
        }
    }
}

// ===========================================================================
// Merged scatter from fused QKV output: rope_q + rope_k + transpose_v_new.
// Flat grid 21504 blocks, 256 threads:
//  [0,16384)      rope Q
//  [16384,20480)  rope K
//  [20480,21504)  V transpose (new)
// ===========================================================================
__global__ void scatter_qkv_kernel(
    const float* __restrict__ qkv,
    const float* __restrict__ cosb, const float* __restrict__ sinb,
    __nv_bfloat16* __restrict__ qh, __nv_bfloat16* __restrict__ ql,
    __nv_bfloat16* __restrict__ kh, __nv_bfloat16* __restrict__ kl,
    __nv_bfloat16* __restrict__ vth, __nv_bfloat16* __restrict__ vtl)
{
    __shared__ float t[32][33];
    const int bid = blockIdx.x;
    const int tid = threadIdx.x;

    if (bid < 16384) {                    // rope Q
        int idx = bid * 256 + tid;
        int d = idx & 63;
        int h = (idx >> 6) & 31;
        int l = (idx >> 11) & 1023;
        int b = idx >> 21;
        size_t rb = (size_t)(b * L_ + l) * QKVW + h * 64;
        float v  = qkv[rb + d];
        int  d2  = (d < 32) ? d + 32 : d - 32;
        float vp = qkv[rb + d2];
        float rot = (d < 32) ? -vp : vp;
        float o = v * cosb[l * 64 + d] + rot * sinb[l * 64 + d];
        __nv_bfloat16 hi, lo;
        split_bf16(o, hi, lo);
        size_t dst = (((size_t)(b * NH_ + h)) * L_ + l) * D_ + d;
        qh[dst] = hi;
        ql[dst] = lo;
    } else if (bid < 20480) {             // rope K
        int idx = (bid - 16384) * 256 + tid;
        int d = idx & 63;
        int h = (idx >> 6) & 7;
        int l = (idx >> 9) & 1023;
        int b = idx >> 19;
        size_t rb = (size_t)(b * L_ + l) * QKVW + 2048 + h * 64;
        float v  = qkv[rb + d];
        int  d2  = (d < 32) ? d + 32 : d - 32;
        float vp = qkv[rb + d2];
        float rot = (d < 32) ? -vp : vp;
        float o = v * cosb[l * 64 + d] + rot * sinb[l * 64 + d];
        __nv_bfloat16 hi, lo;
        split_bf16(o, hi, lo);
        size_t dst = (((size_t)(b * NKV_ + h)) * T_ + (P_ + l)) * D_ + d;
        kh[dst] = hi;
        kl[dst] = lo;
    } else {                              // V transpose (new)
        int lb = bid - 20480;
        int d0 = (lb & 1) * 32;
        int l0 = ((lb >> 1) & 31) * 32;
        int bh = lb >> 6;
        int b = bh >> 3, h = bh & 7;
        int tx = tid & 31, ty = tid >> 5;
#pragma unroll
        for (int i = 0; i < 4; i++)
            t[ty + 8 * i][tx] =
                qkv[(size_t)(b * L_ + l0 + ty + 8 * i) * QKVW + 2560 + h * 64 + d0 + tx];
        __syncthreads();
#pragma unroll
        for (int i = 0; i < 4; i++) {
            float a = t[tx][ty + 8 * i];
            __nv_bfloat16 hi, lo;
            split_bf16(a, hi, lo);
            size_t dst = (((size_t)(b * NKV_ + h)) * D_ + d0 + ty + 8 * i) * T_ +
                         P_ + l0 + tx;
            vth[dst] = hi;
            vtl[dst] = lo;
        }
    }
}

// ===========================================================================
// Merged past-KV processing: copy_past_k + transpose_v_past.
// Flat grid 5120 blocks: [0,4096) K copy, [4096,5120) V transpose.
// ===========================================================================
__global__ void scatter_past_kernel(
    const float* __restrict__ pk, const float* __restrict__ pv,
    __nv_bfloat16* __restrict__ kh, __nv_bfloat16* __restrict__ kl,
    __nv_bfloat16* __restrict__ vth, __nv_bfloat16* __restrict__ vtl)
{
    __shared__ float t[32][33];
    const int bid = blockIdx.x;
    const int tid = threadIdx.x;

    if (bid < 4096) {                     // past K copy+split
        int idx = bid * 256 + tid;
        int d = idx & 63;
        int tt = (idx >> 6) & 1023;
        int h = (idx >> 16) & 7;
        int b = idx >> 19;
        __nv_bfloat16 hi, lo;
        split_bf16(pk[idx], hi, lo);
        size_t dst = (((size_t)(b * NKV_ + h)) * T_ + tt) * D_ + d;
        kh[dst] = hi;
        kl[dst] = lo;
    } else {                              // past V transpose
        int lb = bid - 4096;
        int d0 = (lb & 1) * 32;
        int l0 = ((lb >> 1) & 31) * 32;
        int bh = lb >> 6;
        int tx = tid & 31, ty = tid >> 5;
#pragma unroll
        for (int i = 0; i < 4; i++)
            t[ty + 8 * i][tx] =
                pv[((size_t)bh * P_ + l0 + ty + 8 * i) * D_ + d0 + tx];
        __syncthreads();
#pragma unroll
        for (int i = 0; i < 4; i++) {
            float a = t[tx][ty + 8 * i];
            __nv_bfloat16 hi, lo;
            split_bf16(a, hi, lo);
            size_t dst = ((size_t)bh * D_ + d0 + ty + 8 * i) * T_ + l0 + tx;
            vth[dst] = hi;
            vtl[dst] = lo;
        }
    }
}

// ===========================================================================
// Tensor-core flash attention (unchanged from R8/R9)
// ===========================================================================
#define VROW   72
#define QT_B   (128 * VROW * 2)
#define KT_B   (64 * VROW * 2)
#define KVBUF  (4 * KT_B)
#define ATTN_SMEM (2 * QT_B + 2 * KVBUF)

__global__ __launch_bounds__(256) void attn_mma_kernel(
    const __nv_bfloat16* __restrict__ Qh, const __nv_bfloat16* __restrict__ Ql,
    const __nv_bfloat16* __restrict__ Kh, const __nv_bfloat16* __restrict__ Kl,
    const __nv_bfloat16* __restrict__ Vth, const __nv_bfloat16* __restrict__ Vtl,
    __nv_bfloat16* __restrict__ Oh, __nv_bfloat16* __restrict__ Ol)
{
    extern __shared__ char smem[];
    const uint32_t sb = smem_to_u32(smem);
    const uint32_t sQh = sb;
    const uint32_t sQl = sb + QT_B;
    const uint32_t sKV = sb + 2 * QT_B;

    const int tid = threadIdx.x;
    const int lid = tid & 31;
    const int wid = tid >> 5;
    const int qb  = (L_ / 128 - 1) - blockIdx.x;
    const int h   = blockIdx.y;
    const int b   = blockIdx.z;
    const int hk  = h >> 2;
    const int q0  = qb * 128;
    const int ntiles = (P_ + q0 + 128) / 64;

    const int arow = (lid & 7) + ((lid >> 3) & 1) * 8;
    const int akof = (lid >> 4) * 8;
    const int brow = (lid & 7) + (lid >> 4) * 8;
    const int bkof = ((lid >> 3) & 1) * 8;

    const __nv_bfloat16* qh_base = Qh + ((size_t)(b * NH_ + h) * L_ + q0) * D_;
    const __nv_bfloat16* ql_base = Ql + ((size_t)(b * NH_ + h) * L_ + q0) * D_;
    const __nv_bfloat16* kh_base = Kh + (size_t)(b * NKV_ + hk) * T_ * D_;
    const __nv_bfloat16* kl_base = Kl + (size_t)(b * NKV_ + hk) * T_ * D_;
    const __nv_bfloat16* vh_base = Vth + (size_t)(b * NKV_ + hk) * D_ * T_;
    const __nv_bfloat16* vl_base = Vtl + (size_t)(b * NKV_ + hk) * D_ * T_;

    const int ltile = tid >> 6;
    const int lsub  = tid & 63;
    const __nv_bfloat16* kvg =
        (ltile == 0) ? kh_base : (ltile == 1) ? kl_base :
        (ltile == 2) ? vh_base : vl_base;
    const bool isV = (ltile >= 2);
    const uint32_t kvs_off = (uint32_t)(ltile * KT_B);

    {
        const uint32_t db = sKV + kvs_off;
#pragma unroll
        for (int i = 0; i < 8; i++) {
            int chunk = lsub + i * 64;
            int r = chunk >> 3, c = chunk & 7;
            const __nv_bfloat16* src = isV
                ? kvg + (size_t)r * T_ + c * 8
                : kvg + (size_t)r * D_ + c * 8;
            cp_async16(db + (uint32_t)(r * 144 + c * 16), src);
        }
        CP_COMMIT();
    }

#pragma unroll
    for (int t = 0; t < 2; t++) {
        const __nv_bfloat16* src = t ? ql_base : qh_base;
        const uint32_t dstb = t ? sQl : sQh;
#pragma unroll
        for (int i = 0; i < 4; i++) {
            int chunk = tid + i * 256;
            int r = chunk >> 3, c = chunk & 7;
            uint4 v = *(const uint4*)(src + (size_t)r * D_ + c * 8);
            *(uint4*)(smem + (dstb - sb) + r * 144 + c * 16) = v;
        }
    }

    float o[8][4];
#pragma unroll
    for (int ni = 0; ni < 8; ni++)
#pragma unroll
        for (int u = 0; u < 4; u++) o[ni][u] = 0.f;
    float m1 = -1e30f, m2 = -1e30f, l1 = 0.f, l2 = 0.f;

    const int qi1 = q0 + wid * 16 + (lid >> 2);
    const int qi2 = qi1 + 8;
    const int lim1 = qi1 + P_;
    const int lim2 = qi2 + P_;

    for (int kt = 0; kt < ntiles; kt++) {
        if (kt + 1 < ntiles) {
            const uint32_t db = sKV + ((kt + 1) & 1) * KVBUF + kvs_off;
            const int t0 = (kt + 1) * 64;
#pragma unroll
            for (int i = 0; i < 8; i++) {
                int chunk = lsub + i * 64;
                int r = chunk >> 3, c = chunk & 7;
                const __nv_bfloat16* src = isV
                    ? kvg + (size_t)r * T_ + t0 + c * 8
                    : kvg + (size_t)(t0 + r) * D_ + c * 8;
                cp_async16(db + (uint32_t)(r * 144 + c * 16), src);
            }
            CP_COMMIT();
            CP_WAIT1();
        } else {
            CP_WAIT0();
        }
        __syncthreads();

        const uint32_t ub  = sKV + (kt & 1) * KVBUF;
        const uint32_t uKh = ub;
        const uint32_t uKl = ub + KT_B;
        const uint32_t uVh = ub + 2 * KT_B;
        const uint32_t uVl = ub + 3 * KT_B;

        float s[8][4];
#pragma unroll
        for (int ni = 0; ni < 8; ni++)
#pragma unroll
            for (int u = 0; u < 4; u++) s[ni][u] = 0.f;

#pragma unroll
        for (int ks = 0; ks < 4; ks++) {
            uint32_t ahf[4], alf[4];
            uint32_t ao = (uint32_t)((wid * 16 + arow) * 144 + (ks * 16 + akof) * 2);
            ldsm_x4(ahf, sQh + ao);
            ldsm_x4(alf, sQl + ao);
#pragma unroll
            for (int pr = 0; pr < 4; pr++) {
                uint32_t bhf[4], blf[4];
                uint32_t bo = (uint32_t)((pr * 16 + brow) * 144 + (ks * 16 + bkof) * 2);
                ldsm_x4(bhf, uKh + bo);
                ldsm_x4(blf, uKl + bo);
#pragma unroll
                for (int t = 0; t < 2; t++) {
                    int ni = 2 * pr + t, s2 = t * 2;
                    mma_bf16(s[ni], ahf, bhf[s2], bhf[s2 + 1]);
                    mma_bf16(s[ni], ahf, blf[s2], blf[s2 + 1]);
                    mma_bf16(s[ni], alf, bhf[s2], bhf[s2 + 1]);
                }
            }
        }

#pragma unroll
        for (int ni = 0; ni < 8; ni++)
#pragma unroll
            for (int u = 0; u < 4; u++) s[ni][u] *= SCALE_;

        if (kt >= ntiles - 2) {
            int jc = kt * 64 + 2 * (lid & 3);
#pragma unroll
            for (int ni = 0; ni < 8; ni++) {
                int j = jc + 8 * ni;
                if (j     > lim1) s[ni][0] = -1e30f;
                if (j + 1 > lim1) s[ni][1] = -1e30f;
                if (j     > lim2) s[ni][2] = -1e30f;
                if (j + 1 > lim2) s[ni][3] = -1e30f;
            }
        }

        float mx1 = -1e30f, mx2 = -1e30f;
#pragma unroll
        for (int ni = 0; ni < 8; ni++) {
            mx1 = fmaxf(mx1, fmaxf(s[ni][0], s[ni][1]));
            mx2 = fmaxf(mx2, fmaxf(s[ni][2], s[ni][3]));
        }
        mx1 = fmaxf(mx1, __shfl_xor_sync(0xffffffffu, mx1, 1));
        mx1 = fmaxf(mx1, __shfl_xor_sync(0xffffffffu, mx1, 2));
        mx2 = fmaxf(mx2, __shfl_xor_sync(0xffffffffu, mx2, 1));
        mx2 = fmaxf(mx2, __shfl_xor_sync(0xffffffffu, mx2, 2));

        float mn1 = fmaxf(m1, mx1), mn2 = fmaxf(m2, mx2);
        float c1 = __expf(m1 - mn1), c2 = __expf(m2 - mn2);
        m1 = mn1; m2 = mn2;

        float p1 = 0.f, p2 = 0.f;
#pragma unroll
        for (int ni = 0; ni < 8; ni++) {
            s[ni][0] = __expf(s[ni][0] - mn1);
            s[ni][1] = __expf(s[ni][1] - mn1);
            s[ni][2] = __expf(s[ni][2] - mn2);
            s[ni][3] = __expf(s[ni][3] - mn2);
            p1 += s[ni][0] + s[ni][1];
            p2 += s[ni][2] + s[ni][3];
        }
        p1 += __shfl_xor_sync(0xffffffffu, p1, 1);
        p1 += __shfl_xor_sync(0xffffffffu, p1, 2);
        p2 += __shfl_xor_sync(0xffffffffu, p2, 1);
        p2 += __shfl_xor_sync(0xffffffffu, p2, 2);
        l1 = l1 * c1 + p1;
        l2 = l2 * c2 + p2;

#pragma unroll
        for (int ni = 0; ni < 8; ni++) {
            o[ni][0] *= c1; o[ni][1] *= c1;
            o[ni][2] *= c2; o[ni][3] *= c2;
        }

#pragma unroll
        for (int ks = 0; ks < 4; ks++) {
            uint32_t aPh[4], aPl[4];
            pack2_split(s[2 * ks][0],     s[2 * ks][1],     aPh[0], aPl[0]);
            pack2_split(s[2 * ks][2],     s[2 * ks][3],     aPh[1], aPl[1]);
            pack2_split(s[2 * ks + 1][0], s[2 * ks + 1][1], aPh[2], aPl[2]);
            pack2_split(s[2 * ks + 1][2], s[2 * ks + 1][3], aPh[3], aPl[3]);
#pragma unroll
            for (int pr = 0; pr < 4; pr++) {
                uint32_t bvh[4], bvl[4];
                uint32_t bo = (uint32_t)((pr * 16 + brow) * 144 + (ks * 16 + bkof) * 2);
                ldsm_x4(bvh, uVh + bo);
                ldsm_x4(bvl, uVl + bo);
#pragma unroll
                for (int t = 0; t < 2; t++) {
                    int ni = 2 * pr + t, s2 = t * 2;
                    mma_bf16(o[ni], aPh, bvh[s2], bvh[s2 + 1]);
                    mma_bf16(o[ni], aPh, bvl[s2], bvl[s2 + 1]);
                    mma_bf16(o[ni], aPl, bvh[s2], bvh[s2 + 1]);
                }
            }
        }
        __syncthreads();
    }

    float inv1 = 1.f / l1, inv2 = 1.f / l2;
    size_t base1 = (((size_t)b * L_ + qi1) * NH_ + h) * D_;
    size_t base2 = (((size_t)b * L_ + qi2) * NH_ + h) * D_;
#pragma unroll
    for (int ni = 0; ni < 8; ni++) {
        int d = 8 * ni + 2 * (lid & 3);
        uint32_t uh, ul;
        pack2_split(o[ni][0] * inv1, o[ni][1] * inv1, uh, ul);
        *(uint32_t*)(Oh + base1 + d) = uh;
        *(uint32_t*)(Ol + base1 + d) = ul;
        pack2_split(o[ni][2] * inv2, o[ni][3] * inv2, uh, ul);
        *(uint32_t*)(Oh + base2 + d) = uh;
        *(uint32_t*)(Ol + base2 + d) = ul;
    }
}

// ===========================================================================
// Launch
// ===========================================================================
extern "C" void kernel_launch(void* const* d_in, const int* in_sizes, int n_in,
                              void* d_out, int out_size)
{
    const float* x      = (const float*)d_in[0];
    const float* cosb   = (const float*)d_in[2];
    const float* sinb   = (const float*)d_in[3];
    const float* past_k = (const float*)d_in[4];
    const float* past_v = (const float*)d_in[5];
    const float* Wq     = (const float*)d_in[6];
    const float* bq     = (const float*)d_in[7];
    const float* Wk     = (const float*)d_in[8];
    const float* bk     = (const float*)d_in[9];
    const float* Wv     = (const float*)d_in[10];
    const float* bv     = (const float*)d_in[11];
    const float* Wo     = (const float*)d_in[12];
    float* out          = (float*)d_out;

    float *qkvlin, *bcat;
    cudaGetSymbolAddress((void**)&qkvlin, g_qkvlin);
    cudaGetSymbolAddress((void**)&bcat,   g_bcat);

    __nv_bfloat16 *xh, *xl, *ath, *atl;
    __nv_bfloat16 *wch, *wcl, *woh, *wol;
    __nv_bfloat16 *qh, *ql, *kh, *kl, *vth, *vtl;
    cudaGetSymbolAddress((void**)&xh,  g_xh);
    cudaGetSymbolAddress((void**)&xl,  g_xl);
    cudaGetSymbolAddress((void**)&ath, g_ath);
    cudaGetSymbolAddress((void**)&atl, g_atl);
    cudaGetSymbolAddress((void**)&wch, g_wcat_h);
    cudaGetSymbolAddress((void**)&wcl, g_wcat_l);
    cudaGetSymbolAddress((void**)&woh, g_wot_h);
    cudaGetSymbolAddress((void**)&wol, g_wot_l);
    cudaGetSymbolAddress((void**)&qh,  g_qh);
    cudaGetSymbolAddress((void**)&ql,  g_ql);
    cudaGetSymbolAddress((void**)&kh,  g_kh);
    cudaGetSymbolAddress((void**)&kl,  g_kl);
    cudaGetSymbolAddress((void**)&vth, g_vth);
    cudaGetSymbolAddress((void**)&vtl, g_vtl);

    const int M = B_ * L_;  // 2048

    cudaFuncSetAttribute(gemm_mma3_kernel,
                         cudaFuncAttributeMaxDynamicSharedMemorySize, GEMM3_SMEM);
    cudaFuncSetAttribute(attn_mma_kernel,
                         cudaFuncAttributeMaxDynamicSharedMemorySize, ATTN_SMEM);

    // 1. all weight/bias/x prep in one launch
    prep_w_kernel<<<14348, 256>>>(Wq, Wk, Wv, Wo, bq, bk, bv, x,
                                  wch, wcl, woh, wol, bcat, xh, xl);

    // 2. past KV processing (independent of GEMM)
    scatter_past_kernel<<<5120, 256>>>(past_k, past_v, kh, kl, vth, vtl);

    // 3. fused QKV projection [2048, 3072]
    gemm_mma3_kernel<<<dim3(QKVW / 128, M / 128), 256, GEMM3_SMEM>>>(
        xh, xl, wch, wcl, bcat, qkvlin, QKVW, HID_);

    // 4. rope Q/K + V transpose from fused output
    scatter_qkv_kernel<<<21504, 256>>>(qkvlin, cosb, sinb,
                                       qh, ql, kh, kl, vth, vtl);

    // 5. attention
    attn_mma_kernel<<<dim3(L_ / 128, NH_, B_), 256, ATTN_SMEM>>>(
        qh, ql, kh, kl, vth, vtl, ath, atl);

    // 6. output projection [2048, 2048]
    gemm_mma3_kernel<<<dim3(HID_ / 128, M / 128), 256, GEMM3_SMEM>>>(
        ath, atl, woh, wol, nullptr, out, HID_, HID_);
}